// round 8
// baseline (speedup 1.0000x reference)
#include <cuda_runtime.h>

// Fused 3-phase LSTM (cent H=32 x100, enc H=64 x20, dec H=96 x30).
// R7 = R6 (2 independent 256-thread groups, named barriers, double-buffered
// h/x, HW tanh activations) + STRUCTURAL MUFU/FMA overlap: each step's
// k-loop is split by hidden row; the last row's k-loop is unrolled in 8-k
// chunks with the finished rows' activations injected between chunks, so
// MUFU issues interleave with the FFMA2 stream inside each thread.

#define TPB  512
#define BT   64
#define GBT  32      // batch columns per group

typedef unsigned long long ull;

// ---------------- packed f32x2 helpers ----------------
__device__ __forceinline__ ull pk2(float lo, float hi) {
    ull r; asm("mov.b64 %0, {%1, %2};" : "=l"(r) : "f"(lo), "f"(hi)); return r;
}
__device__ __forceinline__ ull dup2(float x) {
    ull r; asm("mov.b64 %0, {%1, %1};" : "=l"(r) : "f"(x)); return r;
}
__device__ __forceinline__ ull fma2(ull a, ull b, ull c) {
    ull d; asm("fma.rn.f32x2 %0, %1, %2, %3;" : "=l"(d) : "l"(a), "l"(b), "l"(c)); return d;
}
__device__ __forceinline__ float2 upk(ull a) {
    float lo, hi; asm("mov.b64 {%0, %1}, %2;" : "=f"(lo), "=f"(hi) : "l"(a));
    return make_float2(lo, hi);
}

// ---------------- activations via HW tanh (1 MUFU each) ----------------
__device__ __forceinline__ float tanh_(float x){
    float r; asm("tanh.approx.f32 %0, %1;" : "=f"(r) : "f"(x)); return r;
}
__device__ __forceinline__ float sigm(float x){
    return fmaf(0.5f, tanh_(0.5f * x), 0.5f);
}

// one LSTM cell: gates -> (new c in place, returns new h). 5 MUFU.
__device__ __forceinline__ float cellact(ull aifv, ull agov, float& c) {
    float2 sif = upk(aifv);
    float2 sgo = upk(agov);
    float ig = sigm(sif.x);
    float fg = sigm(sif.y);
    float gg = tanh_(sgo.x);
    float og = sigm(sgo.y);
    float cn = fmaf(fg, c, ig * gg);
    c = cn;
    return og * tanh_(cn);
}

// ---------------- group-local named barrier (256 threads) ----------------
__device__ __forceinline__ void gbar(int g) {
    asm volatile("bar.sync %0, %1;" :: "r"(g + 1), "r"(256) : "memory");
}

// ---------------- SMEM layout (float offsets) ----------------
#define WS_D_OFF  0        // decoder weights [0,36864)
#define WS_C_OFF  0        // cent weights   [0,4096)
#define WS_E_OFF  4096     // enc weights    [4096,20480)
#define CS_OFF    20480    // c staging [96][64] = 6144 -> [20480,26624)
#define HS_OFF    36864    // h state: 2 buffers x [96][64] = 2*6144
#define XS_OFF    49152    // dup'd x: 2 buffers x 128 ull = 512 floats
#define BPKC_OFF  49664    // cent bias:  64 ull
#define IPKC_OFF  49792    // cent Wih:  128 ull
#define BPKE_OFF  50048    // enc bias:  128 ull
#define IPKE_OFF  50304    // enc Wih:   256 ull
#define BPKD_OFF  50816    // dec bias:  192 ull
#define WEMB_OFF  51200    // 96 float2
#define BEMB_OFF  51392
#define SMEM_FLOATS 51396
#define SMEM_BYTES  (SMEM_FLOATS * 4)

// ---------------- weight/bias staging (CTA-wide) ----------------
template<int H>
__device__ __forceinline__ void load_W(float* __restrict__ Ws,
                                       const float* __restrict__ Whh,
                                       const float* __restrict__ Wih, int tid)
{
    constexpr int total = 4 * H * H;
    for (int s = tid; s < total; s += TPB) {
        int row = s / H;
        int k   = s - row * H;
        int g   = row / H;
        int j   = row - g * H;
        float v = Whh[s];
        if (Wih) v += Wih[s];
        Ws[k * (4 * H) + j * 4 + g] = v;
    }
}

template<int H>
__device__ __forceinline__ void load_bias(ull* __restrict__ Bpk,
                                          const float* __restrict__ bih,
                                          const float* __restrict__ bhh, int tid)
{
    for (int j = tid; j < H; j += TPB) {
        Bpk[j * 2 + 0] = pk2(bih[j] + bhh[j],             bih[H + j] + bhh[H + j]);
        Bpk[j * 2 + 1] = pk2(bih[2*H + j] + bhh[2*H + j], bih[3*H + j] + bhh[3*H + j]);
    }
}

template<int H>
__device__ __forceinline__ void load_ih(ull* __restrict__ Ipk,
                                        const float* __restrict__ Wih, int tid)
{
    for (int t = tid; t < 2 * H; t += TPB) {
        int j = t >> 1, inp = t & 1;
        Ipk[(j * 2 + inp) * 2 + 0] = pk2(Wih[(0*H + j) * 2 + inp], Wih[(1*H + j) * 2 + inp]);
        Ipk[(j * 2 + inp) * 2 + 1] = pk2(Wih[(2*H + j) * 2 + inp], Wih[(3*H + j) * 2 + inp]);
    }
}

// ---------------- pack h operands for one k ----------------
template<int NB>
__device__ __forceinline__ void load_hpack(const float* __restrict__ hb, ull (&hp)[NB]) {
    if constexpr (NB == 4) {
        float4 hv = *(const float4*)hb;
        hp[0] = dup2(hv.x); hp[1] = dup2(hv.y); hp[2] = dup2(hv.z); hp[3] = dup2(hv.w);
    } else {
        float2 hv = *(const float2*)hb;
        hp[0] = dup2(hv.x); hp[1] = dup2(hv.y);
    }
}

// ---------------- one full step: split k-loop + injected activations ----------------
// Rows j0..j0+NH-1; loop1 covers NH-1 rows, loop2 covers the last row with
// the loop1 cells' activations injected between its unrolled 8-k chunks.
// Hr = current h read base (+bcol), Hw = next h write base (+j0 row,+bcol).
template<int H, int NH, int NB>
__device__ __forceinline__ void step_compute(const float* __restrict__ Ws,
                                             const float* __restrict__ Hr,
                                             float* __restrict__ Hw,
                                             int j0,
                                             ull (&aif)[NH][NB], ull (&ago)[NH][NB],
                                             float (&cr)[NH][NB])
{
    constexpr int N1 = NH - 1;
    static_assert(N1 >= 1 && N1 * NB <= H / 8, "inject budget");

    // ---- loop1: rows j0..j0+N1-1 over all k ----
    {
        const float* wb = Ws + j0 * 4;
        #pragma unroll 4
        for (int k = 0; k < H; k++) {
            ull hp[NB];
            load_hpack<NB>(Hr + k * BT, hp);
            #pragma unroll
            for (int i = 0; i < N1; i++) {
                ulonglong2 w = *(const ulonglong2*)(wb + k * (4 * H) + i * 4);
                #pragma unroll
                for (int b = 0; b < NB; b++) {
                    aif[i][b] = fma2(w.x, hp[b], aif[i][b]);
                    ago[i][b] = fma2(w.y, hp[b], ago[i][b]);
                }
            }
        }
    }

    // ---- loop2: last row, 8-k chunks, inject loop1 activations ----
    {
        const float* wbL = Ws + (j0 + N1) * 4;
        #pragma unroll
        for (int c = 0; c < H / 8; c++) {
            #pragma unroll
            for (int kk = 0; kk < 8; kk++) {
                int k = c * 8 + kk;
                ull hp[NB];
                load_hpack<NB>(Hr + k * BT, hp);
                ulonglong2 w = *(const ulonglong2*)(wbL + k * (4 * H));
                #pragma unroll
                for (int b = 0; b < NB; b++) {
                    aif[N1][b] = fma2(w.x, hp[b], aif[N1][b]);
                    ago[N1][b] = fma2(w.y, hp[b], ago[N1][b]);
                }
            }
            if (c < N1 * NB) {     // compile-time folded per unrolled chunk
                int ci = c / NB, cb = c % NB;
                Hw[ci * BT + cb] = cellact(aif[ci][cb], ago[ci][cb], cr[ci][cb]);
            }
        }
    }

    // ---- last row's activations (exposed) ----
    {
        float hn[NB];
        #pragma unroll
        for (int b = 0; b < NB; b++)
            hn[b] = cellact(aif[N1][b], ago[N1][b], cr[N1][b]);
        if constexpr (NB == 4)
            *(float4*)(Hw + N1 * BT) = make_float4(hn[0], hn[1], hn[2], hn[3]);
        else
            *(float2*)(Hw + N1 * BT) = make_float2(hn[0], hn[1]);
    }
}

// ---------------- one input-driven LSTM phase, group-local ----------------
template<int H, int NH, int NB, int HOFF, int T>
__device__ __forceinline__ void lstm_phase(float* __restrict__ S,
                                           const float* __restrict__ xsrc, int xstride,
                                           int B, int bbase, int g, int tid_g,
                                           int wsOff, int bpkOff, int ipkOff)
{
    constexpr int BG = GBT / NB;
    static_assert((H / NH) * BG == 256, "group thread map");
    int hg = tid_g / BG, bg = tid_g % BG;
    int j0 = hg * NH, bcol = g * GBT + bg * NB;

    float* Ws = S + wsOff;
    float* Cs = S + CS_OFF;
    float* H0 = S + HS_OFF;  float* H1 = H0 + 6144;
    ull*   X0 = (ull*)(S + XS_OFF); ull* X1 = X0 + 128;
    ull*   Bpk = (ull*)(S + bpkOff);
    ull*   Ipk = (ull*)(S + ipkOff);

    float cr[NH][NB];
    #pragma unroll
    for (int i = 0; i < NH; i++)
        #pragma unroll
        for (int b = 0; b < NB; b++) cr[i][b] = 0.0f;

    ull bif[NH], bgo[NH], wif0[NH], wif1[NH], wgo0[NH], wgo1[NH];
    #pragma unroll
    for (int i = 0; i < NH; i++) {
        bif[i]  = Bpk[(j0 + i) * 2 + 0];
        bgo[i]  = Bpk[(j0 + i) * 2 + 1];
        wif0[i] = Ipk[((j0 + i) * 2 + 0) * 2 + 0];
        wgo0[i] = Ipk[((j0 + i) * 2 + 0) * 2 + 1];
        wif1[i] = Ipk[((j0 + i) * 2 + 1) * 2 + 0];
        wgo1[i] = Ipk[((j0 + i) * 2 + 1) * 2 + 1];
    }

    // initial x stage (group-local; 32 stager threads)
    bool stager = (tid_g < GBT);
    int  scol = g * GBT + tid_g;
    int  bb = bbase + scol; if (bb >= B) bb = B - 1;
    if (stager) {
        float2 x = *(const float2*)&xsrc[(size_t)bb * xstride];
        X0[2 * scol + 0] = pk2(x.x, x.x);
        X0[2 * scol + 1] = pk2(x.y, x.y);
    }
    gbar(g);

    float* Hc = H0; float* Hn = H1;
    ull*   Xc = X0; ull*   Xn = X1;

    for (int t = 0; t < T; t++) {
        float2 xnv;
        bool st = stager && (t + 1 < T);
        if (st)   // prefetch next x early; LDG hides under the fma stream
            xnv = *(const float2*)&xsrc[(size_t)bb * xstride + (size_t)(t + 1) * 2];

        // init accumulators with bias + x contribution
        ull aif[NH][NB], ago[NH][NB];
        #pragma unroll
        for (int b = 0; b < NB; b++) {
            ull xa = Xc[2 * (bcol + b) + 0];
            ull xb = Xc[2 * (bcol + b) + 1];
            #pragma unroll
            for (int i = 0; i < NH; i++) {
                aif[i][b] = fma2(wif0[i], xa, fma2(wif1[i], xb, bif[i]));
                ago[i][b] = fma2(wgo0[i], xa, fma2(wgo1[i], xb, bgo[i]));
            }
        }

        step_compute<H, NH, NB>(Ws, Hc + HOFF * BT + bcol,
                                Hn + (HOFF + j0) * BT + bcol, j0, aif, ago, cr);

        if (st) {
            Xn[2 * scol + 0] = pk2(xnv.x, xnv.x);
            Xn[2 * scol + 1] = pk2(xnv.y, xnv.y);
        }
        gbar(g);   // one barrier per step (double-buffered h/x)
        { float* tf = Hc; Hc = Hn; Hn = tf; }
        { ull*  tx = Xc; Xc = Xn; Xn = tx; }
    }
    // T even for all phases -> final h lands in H0 (decoder's read buffer)

    // stage final c for the decoder
    #pragma unroll
    for (int i = 0; i < NH; i++)
        #pragma unroll
        for (int b = 0; b < NB; b++)
            Cs[(HOFF + j0 + i) * BT + bcol + b] = cr[i][b];
}

// ---------------- main fused kernel ----------------
__global__ void __launch_bounds__(TPB, 1)
lstm_fused_kernel(const float* __restrict__ traj,   // [B,20,2]
                  const float* __restrict__ cl,     // [B,100,2]
                  const float* __restrict__ Wih_c, const float* __restrict__ Whh_c,
                  const float* __restrict__ bih_c, const float* __restrict__ bhh_c,
                  const float* __restrict__ Wih_e, const float* __restrict__ Whh_e,
                  const float* __restrict__ bih_e, const float* __restrict__ bhh_e,
                  const float* __restrict__ Wih_d, const float* __restrict__ Whh_d,
                  const float* __restrict__ bih_d, const float* __restrict__ bhh_d,
                  const float* __restrict__ W_emb, const float* __restrict__ b_emb,
                  float* __restrict__ out, int B)
{
    extern __shared__ float S[];
    int tid   = threadIdx.x;
    int bbase = blockIdx.x * BT;
    int g     = tid >> 8;        // group 0/1 (owns batch cols [32g, 32g+32))
    int tid_g = tid & 255;

    float*  H0   = S + HS_OFF;
    float*  Cs   = S + CS_OFF;
    ull*    BpkD = (ull*)(S + BPKD_OFF);
    float2* Wemb = (float2*)(S + WEMB_OFF);
    float2* Bemb = (float2*)(S + BEMB_OFF);

    // zero h buffer 0 (initial states for both phases; H1 is written before read)
    for (int s = tid; s < 6144; s += TPB) H0[s] = 0.0f;

    // stage BOTH phases' weights/biases up front (CTA-wide)
    load_W<32>(S + WS_C_OFF, Whh_c, nullptr, tid);
    load_W<64>(S + WS_E_OFF, Whh_e, nullptr, tid);
    load_bias<32>((ull*)(S + BPKC_OFF), bih_c, bhh_c, tid);
    load_ih<32>((ull*)(S + IPKC_OFF), Wih_c, tid);
    load_bias<64>((ull*)(S + BPKE_OFF), bih_e, bhh_e, tid);
    load_ih<64>((ull*)(S + IPKE_OFF), Wih_e, tid);
    __syncthreads();

    // anti-phase schedule: g0 cent->enc, g1 enc->cent
    if (g == 0) {
        lstm_phase<32, 2, 2, 64, 100>(S, cl,   200, B, bbase, g, tid_g, WS_C_OFF, BPKC_OFF, IPKC_OFF);
        lstm_phase<64, 2, 4,  0,  20>(S, traj,  40, B, bbase, g, tid_g, WS_E_OFF, BPKE_OFF, IPKE_OFF);
    } else {
        lstm_phase<64, 2, 4,  0,  20>(S, traj,  40, B, bbase, g, tid_g, WS_E_OFF, BPKE_OFF, IPKE_OFF);
        lstm_phase<32, 2, 2, 64, 100>(S, cl,   200, B, bbase, g, tid_g, WS_C_OFF, BPKC_OFF, IPKC_OFF);
    }
    __syncthreads();

    // ---- decoder (H=96), x == h so Wih+Whh fold into one matrix ----
    {
        constexpr int NH = 3, NB = 4, BG = GBT / NB;   // 32 hidden groups x 8 batch groups
        int hg = tid_g / BG, bg = tid_g % BG;
        int j0 = hg * NH, bcol = g * GBT + bg * NB;

        // read c BEFORE load_W<96> clobbers the aliased Cs region
        float cr[NH][NB];
        #pragma unroll
        for (int i = 0; i < NH; i++)
            #pragma unroll
            for (int b = 0; b < NB; b++)
                cr[i][b] = Cs[(j0 + i) * BT + bcol + b];
        __syncthreads();

        load_W<96>(S + WS_D_OFF, Whh_d, Wih_d, tid);
        load_bias<96>(BpkD, bih_d, bhh_d, tid);
        for (int k = tid; k < 96; k += TPB) Wemb[k] = make_float2(W_emb[k], W_emb[96 + k]);
        if (tid == 0) *Bemb = make_float2(b_emb[0], b_emb[1]);
        __syncthreads();
        if (g) __nanosleep(2000);  // bias toward anti-phase lock (harmless)

        const float* Ws = S + WS_D_OFF;
        ull bif[NH], bgo[NH];
        #pragma unroll
        for (int i = 0; i < NH; i++) {
            bif[i] = BpkD[(j0 + i) * 2 + 0];
            bgo[i] = BpkD[(j0 + i) * 2 + 1];
        }

        float* Hc = S + HS_OFF;          // h0 = concat(enc, cent) in buffer 0
        float* Hn = S + HS_OFF + 6144;

        bool projer = (tid_g < GBT);
        int  pcol   = g * GBT + tid_g;   // projected batch col (tid_g<32)
        int  pb     = bbase + pcol;

        for (int t = 0; t < 30; t++) {
            ull aif[NH][NB], ago[NH][NB];
            #pragma unroll
            for (int i = 0; i < NH; i++)
                #pragma unroll
                for (int b = 0; b < NB; b++) { aif[i][b] = bif[i]; ago[i][b] = bgo[i]; }

            step_compute<96, NH, NB>(Ws, Hc + bcol, Hn + j0 * BT + bcol,
                                     j0, aif, ago, cr);
            gbar(g);                      // group's new h visible

            // projection: pos = h_new @ W_emb^T + b_emb (32 threads per group;
            // reads Hn only; next step's writes go to Hc -> no conflict)
            if (projer) {
                float2 acc = *Bemb;
                #pragma unroll 8
                for (int k = 0; k < 96; k++) {
                    float  h = Hn[k * BT + pcol];
                    float2 w = Wemb[k];
                    acc.x = fmaf(h, w.x, acc.x);
                    acc.y = fmaf(h, w.y, acc.y);
                }
                if (pb < B) *(float2*)&out[(size_t)(pb * 30 + t) * 2] = acc;
            }
            { float* tf = Hc; Hc = Hn; Hn = tf; }
        }
    }
}

extern "C" void kernel_launch(void* const* d_in, const int* in_sizes, int n_in,
                              void* d_out, int out_size)
{
    const float* traj  = (const float*)d_in[0];
    const float* cl    = (const float*)d_in[1];
    const float* Wih_c = (const float*)d_in[2];
    const float* Whh_c = (const float*)d_in[3];
    const float* bih_c = (const float*)d_in[4];
    const float* bhh_c = (const float*)d_in[5];
    const float* Wih_e = (const float*)d_in[6];
    const float* Whh_e = (const float*)d_in[7];
    const float* bih_e = (const float*)d_in[8];
    const float* bhh_e = (const float*)d_in[9];
    const float* Wih_d = (const float*)d_in[10];
    const float* Whh_d = (const float*)d_in[11];
    const float* bih_d = (const float*)d_in[12];
    const float* bhh_d = (const float*)d_in[13];
    const float* W_emb = (const float*)d_in[14];
    const float* b_emb = (const float*)d_in[15];

    int B = in_sizes[0] / 40;
    int grid = (B + BT - 1) / BT;

    cudaFuncSetAttribute(lstm_fused_kernel,
                         cudaFuncAttributeMaxDynamicSharedMemorySize, SMEM_BYTES);
    lstm_fused_kernel<<<grid, TPB, SMEM_BYTES>>>(
        traj, cl, Wih_c, Whh_c, bih_c, bhh_c,
        Wih_e, Whh_e, bih_e, bhh_e,
        Wih_d, Whh_d, bih_d, bhh_d,
        W_emb, b_emb, (float*)d_out, B);
}

// round 9
// speedup vs baseline: 1.1594x; 1.1594x over previous
#include <cuda_runtime.h>

// Fused 3-phase LSTM (cent H=32 x100, enc H=64 x20, dec H=96 x30).
// R8 = R6's exact inner loops, but 4 independent groups of 128 threads
// (ONE warp per SMSP per group). No two warps on the same SMSP share a
// barrier -> their MUFU bursts can drift into anti-phase and hide under
// the other warps' FFMA2 streams. Double-buffered h/x, 1 barrier/step,
// HW tanh activations.

#define TPB  512
#define BT   64
#define GBT  16      // batch columns per group

typedef unsigned long long ull;

// ---------------- packed f32x2 helpers ----------------
__device__ __forceinline__ ull pk2(float lo, float hi) {
    ull r; asm("mov.b64 %0, {%1, %2};" : "=l"(r) : "f"(lo), "f"(hi)); return r;
}
__device__ __forceinline__ ull dup2(float x) {
    ull r; asm("mov.b64 %0, {%1, %1};" : "=l"(r) : "f"(x)); return r;
}
__device__ __forceinline__ ull fma2(ull a, ull b, ull c) {
    ull d; asm("fma.rn.f32x2 %0, %1, %2, %3;" : "=l"(d) : "l"(a), "l"(b), "l"(c)); return d;
}
__device__ __forceinline__ float2 upk(ull a) {
    float lo, hi; asm("mov.b64 {%0, %1}, %2;" : "=f"(lo), "=f"(hi) : "l"(a));
    return make_float2(lo, hi);
}

// ---------------- activations via HW tanh (1 MUFU each) ----------------
__device__ __forceinline__ float tanh_(float x){
    float r; asm("tanh.approx.f32 %0, %1;" : "=f"(r) : "f"(x)); return r;
}
__device__ __forceinline__ float sigm(float x){
    return fmaf(0.5f, tanh_(0.5f * x), 0.5f);
}

// ---------------- group-local named barrier (128 threads) ----------------
__device__ __forceinline__ void gbar(int g) {
    asm volatile("bar.sync %0, %1;" :: "r"(g + 1), "r"(128) : "memory");
}

// ---------------- SMEM layout (float offsets) ----------------
#define WS_D_OFF  0        // decoder weights [0,36864)
#define WS_C_OFF  0        // cent weights   [0,4096)
#define WS_E_OFF  4096     // enc weights    [4096,20480)
#define CS_OFF    20480    // c staging [96][64] = 6144 -> [20480,26624)
#define HS_OFF    36864    // h state: 2 buffers x [96][64] = 2*6144
#define XS_OFF    49152    // dup'd x: 2 buffers x 128 ull = 512 floats
#define BPKC_OFF  49664    // cent bias:  64 ull
#define IPKC_OFF  49792    // cent Wih:  128 ull
#define BPKE_OFF  50048    // enc bias:  128 ull
#define IPKE_OFF  50304    // enc Wih:   256 ull
#define BPKD_OFF  50816    // dec bias:  192 ull
#define WEMB_OFF  51200    // 96 float2
#define BEMB_OFF  51392
#define SMEM_FLOATS 51396
#define SMEM_BYTES  (SMEM_FLOATS * 4)

// ---------------- weight/bias staging (CTA-wide) ----------------
template<int H>
__device__ __forceinline__ void load_W(float* __restrict__ Ws,
                                       const float* __restrict__ Whh,
                                       const float* __restrict__ Wih, int tid)
{
    constexpr int total = 4 * H * H;
    for (int s = tid; s < total; s += TPB) {
        int row = s / H;
        int k   = s - row * H;
        int g   = row / H;
        int j   = row - g * H;
        float v = Whh[s];
        if (Wih) v += Wih[s];
        Ws[k * (4 * H) + j * 4 + g] = v;
    }
}

template<int H>
__device__ __forceinline__ void load_bias(ull* __restrict__ Bpk,
                                          const float* __restrict__ bih,
                                          const float* __restrict__ bhh, int tid)
{
    for (int j = tid; j < H; j += TPB) {
        Bpk[j * 2 + 0] = pk2(bih[j] + bhh[j],             bih[H + j] + bhh[H + j]);
        Bpk[j * 2 + 1] = pk2(bih[2*H + j] + bhh[2*H + j], bih[3*H + j] + bhh[3*H + j]);
    }
}

template<int H>
__device__ __forceinline__ void load_ih(ull* __restrict__ Ipk,
                                        const float* __restrict__ Wih, int tid)
{
    for (int t = tid; t < 2 * H; t += TPB) {
        int j = t >> 1, inp = t & 1;
        Ipk[(j * 2 + inp) * 2 + 0] = pk2(Wih[(0*H + j) * 2 + inp], Wih[(1*H + j) * 2 + inp]);
        Ipk[(j * 2 + inp) * 2 + 1] = pk2(Wih[(2*H + j) * 2 + inp], Wih[(3*H + j) * 2 + inp]);
    }
}

// ---------------- gate matmul: gates += h @ W^T (R6's exact loop) ----------------
template<int H, int NH, int NB>
__device__ __forceinline__ void gates_mm(const float* __restrict__ Ws,
                                         const float* __restrict__ hbase, // Hc+HOFF*BT+bcol
                                         int j0,
                                         ull (&aif)[NH][NB], ull (&ago)[NH][NB])
{
    const float* wb = Ws + j0 * 4;
    #pragma unroll 4
    for (int k = 0; k < H; k++) {
        ull hp[NB];
        if constexpr (NB == 4) {
            float4 hv = *(const float4*)(hbase + k * BT);
            hp[0] = dup2(hv.x); hp[1] = dup2(hv.y); hp[2] = dup2(hv.z); hp[3] = dup2(hv.w);
        } else {
            float2 hv = *(const float2*)(hbase + k * BT);
            hp[0] = dup2(hv.x); hp[1] = dup2(hv.y);
        }
        #pragma unroll
        for (int i = 0; i < NH; i++) {
            ulonglong2 w = *(const ulonglong2*)(wb + k * (4 * H) + i * 4);
            #pragma unroll
            for (int b = 0; b < NB; b++) {
                aif[i][b] = fma2(w.x, hp[b], aif[i][b]);
                ago[i][b] = fma2(w.y, hp[b], ago[i][b]);
            }
        }
    }
}

// ---------------- activations + h store ----------------
template<int NH, int NB>
__device__ __forceinline__ void act_update(ull (&aif)[NH][NB], ull (&ago)[NH][NB],
                                           float (&cr)[NH][NB],
                                           float* __restrict__ Hw) // Hn+(HOFF+j0)*BT+bcol
{
    #pragma unroll
    for (int i = 0; i < NH; i++) {
        float hn[NB];
        #pragma unroll
        for (int b = 0; b < NB; b++) {
            float2 sif = upk(aif[i][b]);
            float2 sgo = upk(ago[i][b]);
            float ig = sigm(sif.x);
            float fg = sigm(sif.y);
            float gg = tanh_(sgo.x);
            float og = sigm(sgo.y);
            float cn = fmaf(fg, cr[i][b], ig * gg);
            cr[i][b] = cn;
            hn[b] = og * tanh_(cn);
        }
        if constexpr (NB == 4)
            *(float4*)(Hw + i * BT) = make_float4(hn[0], hn[1], hn[2], hn[3]);
        else
            *(float2*)(Hw + i * BT) = make_float2(hn[0], hn[1]);
    }
}

// ---------------- one input-driven LSTM phase, group-local ----------------
template<int H, int NH, int NB, int HOFF, int T>
__device__ __forceinline__ void lstm_phase(float* __restrict__ S,
                                           const float* __restrict__ xsrc, int xstride,
                                           int B, int bbase, int g, int tid_g,
                                           int wsOff, int bpkOff, int ipkOff)
{
    constexpr int BG = GBT / NB;
    static_assert((H / NH) * BG == 128, "group thread map");
    int hg = tid_g / BG, bg = tid_g % BG;
    int j0 = hg * NH, bcol = g * GBT + bg * NB;

    float* Ws = S + wsOff;
    float* Cs = S + CS_OFF;
    float* H0 = S + HS_OFF;  float* H1 = H0 + 6144;
    ull*   X0 = (ull*)(S + XS_OFF); ull* X1 = X0 + 128;
    ull*   Bpk = (ull*)(S + bpkOff);
    ull*   Ipk = (ull*)(S + ipkOff);

    float cr[NH][NB];
    #pragma unroll
    for (int i = 0; i < NH; i++)
        #pragma unroll
        for (int b = 0; b < NB; b++) cr[i][b] = 0.0f;

    ull bif[NH], bgo[NH], wif0[NH], wif1[NH], wgo0[NH], wgo1[NH];
    #pragma unroll
    for (int i = 0; i < NH; i++) {
        bif[i]  = Bpk[(j0 + i) * 2 + 0];
        bgo[i]  = Bpk[(j0 + i) * 2 + 1];
        wif0[i] = Ipk[((j0 + i) * 2 + 0) * 2 + 0];
        wgo0[i] = Ipk[((j0 + i) * 2 + 0) * 2 + 1];
        wif1[i] = Ipk[((j0 + i) * 2 + 1) * 2 + 0];
        wgo1[i] = Ipk[((j0 + i) * 2 + 1) * 2 + 1];
    }

    // initial x stage (group-local; GBT stager threads)
    bool stager = (tid_g < GBT);
    int  scol = g * GBT + tid_g;
    int  bb = bbase + scol; if (bb >= B) bb = B - 1;
    if (stager) {
        float2 x = *(const float2*)&xsrc[(size_t)bb * xstride];
        X0[2 * scol + 0] = pk2(x.x, x.x);
        X0[2 * scol + 1] = pk2(x.y, x.y);
    }
    gbar(g);

    float* Hc = H0; float* Hn = H1;
    ull*   Xc = X0; ull*   Xn = X1;

    for (int t = 0; t < T; t++) {
        float2 xnv;
        bool st = stager && (t + 1 < T);
        if (st)   // prefetch next x early; LDG hides under gates_mm
            xnv = *(const float2*)&xsrc[(size_t)bb * xstride + (size_t)(t + 1) * 2];

        ull aif[NH][NB], ago[NH][NB];
        #pragma unroll
        for (int b = 0; b < NB; b++) {
            ull xa = Xc[2 * (bcol + b) + 0];
            ull xb = Xc[2 * (bcol + b) + 1];
            #pragma unroll
            for (int i = 0; i < NH; i++) {
                aif[i][b] = fma2(wif0[i], xa, fma2(wif1[i], xb, bif[i]));
                ago[i][b] = fma2(wgo0[i], xa, fma2(wgo1[i], xb, bgo[i]));
            }
        }
        gates_mm<H, NH, NB>(Ws, Hc + HOFF * BT + bcol, j0, aif, ago);
        act_update<NH, NB>(aif, ago, cr, Hn + (HOFF + j0) * BT + bcol);
        if (st) {
            Xn[2 * scol + 0] = pk2(xnv.x, xnv.x);
            Xn[2 * scol + 1] = pk2(xnv.y, xnv.y);
        }
        gbar(g);   // one barrier per step (double-buffered h/x)
        { float* tf = Hc; Hc = Hn; Hn = tf; }
        { ull*  tx = Xc; Xc = Xn; Xn = tx; }
    }
    // T even for all phases -> final h lands in H0 (decoder's read buffer)

    // stage final c for the decoder
    #pragma unroll
    for (int i = 0; i < NH; i++)
        #pragma unroll
        for (int b = 0; b < NB; b++)
            Cs[(HOFF + j0 + i) * BT + bcol + b] = cr[i][b];
}

// ---------------- main fused kernel ----------------
__global__ void __launch_bounds__(TPB, 1)
lstm_fused_kernel(const float* __restrict__ traj,   // [B,20,2]
                  const float* __restrict__ cl,     // [B,100,2]
                  const float* __restrict__ Wih_c, const float* __restrict__ Whh_c,
                  const float* __restrict__ bih_c, const float* __restrict__ bhh_c,
                  const float* __restrict__ Wih_e, const float* __restrict__ Whh_e,
                  const float* __restrict__ bih_e, const float* __restrict__ bhh_e,
                  const float* __restrict__ Wih_d, const float* __restrict__ Whh_d,
                  const float* __restrict__ bih_d, const float* __restrict__ bhh_d,
                  const float* __restrict__ W_emb, const float* __restrict__ b_emb,
                  float* __restrict__ out, int B)
{
    extern __shared__ float S[];
    int tid   = threadIdx.x;
    int bbase = blockIdx.x * BT;
    int g     = tid >> 7;        // group 0..3 (owns batch cols [16g, 16g+16))
    int tid_g = tid & 127;       // one warp per SMSP per group

    float*  H0   = S + HS_OFF;
    float*  Cs   = S + CS_OFF;
    ull*    BpkD = (ull*)(S + BPKD_OFF);
    float2* Wemb = (float2*)(S + WEMB_OFF);
    float2* Bemb = (float2*)(S + BEMB_OFF);

    // zero h buffer 0 (initial states for both phases; H1 is written before read)
    for (int s = tid; s < 6144; s += TPB) H0[s] = 0.0f;

    // stage BOTH phases' weights/biases up front (CTA-wide)
    load_W<32>(S + WS_C_OFF, Whh_c, nullptr, tid);
    load_W<64>(S + WS_E_OFF, Whh_e, nullptr, tid);
    load_bias<32>((ull*)(S + BPKC_OFF), bih_c, bhh_c, tid);
    load_ih<32>((ull*)(S + IPKC_OFF), Wih_c, tid);
    load_bias<64>((ull*)(S + BPKE_OFF), bih_e, bhh_e, tid);
    load_ih<64>((ull*)(S + IPKE_OFF), Wih_e, tid);
    __syncthreads();

    // anti-phase schedule across groups (plus free-running drift: no two
    // warps of one SMSP share a barrier)
    if (g & 1) {
        lstm_phase<64, 2, 4,  0,  20>(S, traj,  40, B, bbase, g, tid_g, WS_E_OFF, BPKE_OFF, IPKE_OFF);
        lstm_phase<32, 1, 4, 64, 100>(S, cl,   200, B, bbase, g, tid_g, WS_C_OFF, BPKC_OFF, IPKC_OFF);
    } else {
        lstm_phase<32, 1, 4, 64, 100>(S, cl,   200, B, bbase, g, tid_g, WS_C_OFF, BPKC_OFF, IPKC_OFF);
        lstm_phase<64, 2, 4,  0,  20>(S, traj,  40, B, bbase, g, tid_g, WS_E_OFF, BPKE_OFF, IPKE_OFF);
    }
    __syncthreads();

    // ---- decoder (H=96), x == h so Wih+Whh fold into one matrix ----
    {
        constexpr int NH = 3, NB = 4, BG = GBT / NB;   // 32 hidden groups x 4 batch groups
        int hg = tid_g / BG, bg = tid_g % BG;
        int j0 = hg * NH, bcol = g * GBT + bg * NB;

        // read c BEFORE load_W<96> clobbers the aliased Cs region
        float cr[NH][NB];
        #pragma unroll
        for (int i = 0; i < NH; i++)
            #pragma unroll
            for (int b = 0; b < NB; b++)
                cr[i][b] = Cs[(j0 + i) * BT + bcol + b];
        __syncthreads();

        load_W<96>(S + WS_D_OFF, Whh_d, Wih_d, tid);
        load_bias<96>(BpkD, bih_d, bhh_d, tid);
        for (int k = tid; k < 96; k += TPB) Wemb[k] = make_float2(W_emb[k], W_emb[96 + k]);
        if (tid == 0) *Bemb = make_float2(b_emb[0], b_emb[1]);
        __syncthreads();
        __nanosleep((unsigned)(g * 1100));  // seed per-group phase offset

        const float* Ws = S + WS_D_OFF;
        ull bif[NH], bgo[NH];
        #pragma unroll
        for (int i = 0; i < NH; i++) {
            bif[i] = BpkD[(j0 + i) * 2 + 0];
            bgo[i] = BpkD[(j0 + i) * 2 + 1];
        }

        float* Hc = S + HS_OFF;          // h0 = concat(enc, cent) in buffer 0
        float* Hn = S + HS_OFF + 6144;

        bool projer = (tid_g < GBT);
        int  pcol   = g * GBT + tid_g;   // projected batch col (tid_g<16)
        int  pb     = bbase + pcol;

        for (int t = 0; t < 30; t++) {
            ull aif[NH][NB], ago[NH][NB];
            #pragma unroll
            for (int i = 0; i < NH; i++)
                #pragma unroll
                for (int b = 0; b < NB; b++) { aif[i][b] = bif[i]; ago[i][b] = bgo[i]; }

            gates_mm<96, NH, NB>(Ws, Hc + bcol, j0, aif, ago);
            act_update<NH, NB>(aif, ago, cr, Hn + j0 * BT + bcol);
            gbar(g);                      // group's new h visible

            // projection: pos = h_new @ W_emb^T + b_emb (16 threads per group;
            // reads Hn only; next step's writes go to Hc -> no conflict)
            if (projer) {
                float2 acc = *Bemb;
                #pragma unroll 8
                for (int k = 0; k < 96; k++) {
                    float  h = Hn[k * BT + pcol];
                    float2 w = Wemb[k];
                    acc.x = fmaf(h, w.x, acc.x);
                    acc.y = fmaf(h, w.y, acc.y);
                }
                if (pb < B) *(float2*)&out[(size_t)(pb * 30 + t) * 2] = acc;
            }
            { float* tf = Hc; Hc = Hn; Hn = tf; }
        }
    }
}

extern "C" void kernel_launch(void* const* d_in, const int* in_sizes, int n_in,
                              void* d_out, int out_size)
{
    const float* traj  = (const float*)d_in[0];
    const float* cl    = (const float*)d_in[1];
    const float* Wih_c = (const float*)d_in[2];
    const float* Whh_c = (const float*)d_in[3];
    const float* bih_c = (const float*)d_in[4];
    const float* bhh_c = (const float*)d_in[5];
    const float* Wih_e = (const float*)d_in[6];
    const float* Whh_e = (const float*)d_in[7];
    const float* bih_e = (const float*)d_in[8];
    const float* bhh_e = (const float*)d_in[9];
    const float* Wih_d = (const float*)d_in[10];
    const float* Whh_d = (const float*)d_in[11];
    const float* bih_d = (const float*)d_in[12];
    const float* bhh_d = (const float*)d_in[13];
    const float* W_emb = (const float*)d_in[14];
    const float* b_emb = (const float*)d_in[15];

    int B = in_sizes[0] / 40;
    int grid = (B + BT - 1) / BT;

    cudaFuncSetAttribute(lstm_fused_kernel,
                         cudaFuncAttributeMaxDynamicSharedMemorySize, SMEM_BYTES);
    lstm_fused_kernel<<<grid, TPB, SMEM_BYTES>>>(
        traj, cl, Wih_c, Whh_c, bih_c, bhh_c,
        Wih_e, Whh_e, bih_e, bhh_e,
        Wih_d, Whh_d, bih_d, bhh_d,
        W_emb, b_emb, (float*)d_out, B);
}

// round 12
// speedup vs baseline: 1.1804x; 1.0181x over previous
#include <cuda_runtime.h>

// Fused 3-phase LSTM (cent H=32 x100, enc H=64 x20, dec H=96 x30).
// R11 = R8 (4 independent 128-thread groups, one warp per SMSP per group,
// group-local named barriers, double-buffered h/x, HW tanh activations)
// + straggler-warp leveling:
//   - decoder projection split across the group's 4 warps (24-k partials,
//     parity-double-buffered in SMEM, summed after the NEXT step's barrier)
//   - x staging distributed (lanes 0-3 of each warp stage 4 columns)

#define TPB  512
#define BT   64
#define GBT  16      // batch columns per group

typedef unsigned long long ull;

// ---------------- packed f32x2 helpers ----------------
__device__ __forceinline__ ull pk2(float lo, float hi) {
    ull r; asm("mov.b64 %0, {%1, %2};" : "=l"(r) : "f"(lo), "f"(hi)); return r;
}
__device__ __forceinline__ ull dup2(float x) {
    ull r; asm("mov.b64 %0, {%1, %1};" : "=l"(r) : "f"(x)); return r;
}
__device__ __forceinline__ ull fma2(ull a, ull b, ull c) {
    ull d; asm("fma.rn.f32x2 %0, %1, %2, %3;" : "=l"(d) : "l"(a), "l"(b), "l"(c)); return d;
}
__device__ __forceinline__ float2 upk(ull a) {
    float lo, hi; asm("mov.b64 {%0, %1}, %2;" : "=f"(lo), "=f"(hi) : "l"(a));
    return make_float2(lo, hi);
}

// ---------------- activations via HW tanh (1 MUFU each) ----------------
__device__ __forceinline__ float tanh_(float x){
    float r; asm("tanh.approx.f32 %0, %1;" : "=f"(r) : "f"(x)); return r;
}
__device__ __forceinline__ float sigm(float x){
    return fmaf(0.5f, tanh_(0.5f * x), 0.5f);
}

// ---------------- group-local named barrier (128 threads) ----------------
__device__ __forceinline__ void gbar(int g) {
    asm volatile("bar.sync %0, %1;" :: "r"(g + 1), "r"(128) : "memory");
}

// ---------------- SMEM layout (float offsets) ----------------
#define WS_D_OFF  0        // decoder weights [0,36864)
#define WS_C_OFF  0        // cent weights   [0,4096)
#define WS_E_OFF  4096     // enc weights    [4096,20480)
#define CS_OFF    20480    // c staging [96][64] = 6144 -> [20480,26624)
#define HS_OFF    36864    // h state: 2 buffers x [96][64] = 2*6144
#define XS_OFF    49152    // dup'd x: 2 buffers x 128 ull = 512 floats
#define BPKC_OFF  49664    // cent bias:  64 ull
#define IPKC_OFF  49792    // cent Wih:  128 ull
#define BPKE_OFF  50048    // enc bias:  128 ull
#define IPKE_OFF  50304    // enc Wih:   256 ull
#define BPKD_OFF  50816    // dec bias:  192 ull
#define WEMB_OFF  51200    // 96 float2
#define BEMB_OFF  51392    // 1 float2
#define PP_OFF    51394    // proj partials: [4 g][2 par][4 ww][16 col] float2 = 1024 f
#define SMEM_FLOATS 52420
#define SMEM_BYTES  (SMEM_FLOATS * 4)

// ---------------- weight/bias staging (CTA-wide) ----------------
template<int H>
__device__ __forceinline__ void load_W(float* __restrict__ Ws,
                                       const float* __restrict__ Whh,
                                       const float* __restrict__ Wih, int tid)
{
    constexpr int total = 4 * H * H;
    for (int s = tid; s < total; s += TPB) {
        int row = s / H;
        int k   = s - row * H;
        int g   = row / H;
        int j   = row - g * H;
        float v = Whh[s];
        if (Wih) v += Wih[s];
        Ws[k * (4 * H) + j * 4 + g] = v;
    }
}
template<int H>
__device__ __forceinline__ void load_bias(ull* __restrict__ Bpk,
                                          const float* __restrict__ bih,
                                          const float* __restrict__ bhh, int tid)
{
    for (int j = tid; j < H; j += TPB) {
        Bpk[j * 2 + 0] = pk2(bih[j] + bhh[j],             bih[H + j] + bhh[H + j]);
        Bpk[j * 2 + 1] = pk2(bih[2*H + j] + bhh[2*H + j], bih[3*H + j] + bhh[3*H + j]);
    }
}
template<int H>
__device__ __forceinline__ void load_ih(ull* __restrict__ Ipk,
                                        const float* __restrict__ Wih, int tid)
{
    for (int t = tid; t < 2 * H; t += TPB) {
        int j = t >> 1, inp = t & 1;
        Ipk[(j * 2 + inp) * 2 + 0] = pk2(Wih[(0*H + j) * 2 + inp], Wih[(1*H + j) * 2 + inp]);
        Ipk[(j * 2 + inp) * 2 + 1] = pk2(Wih[(2*H + j) * 2 + inp], Wih[(3*H + j) * 2 + inp]);
    }
}

// ---------------- gate matmul: gates += h @ W^T (champion inner loop) ----------------
template<int H, int NH, int NB>
__device__ __forceinline__ void gates_mm(const float* __restrict__ Ws,
                                         const float* __restrict__ hbase, int j0,
                                         ull (&aif)[NH][NB], ull (&ago)[NH][NB])
{
    const float* wb = Ws + j0 * 4;
    #pragma unroll 4
    for (int k = 0; k < H; k++) {
        ull hp[NB];
        float4 hv = *(const float4*)(hbase + k * BT);
        hp[0] = dup2(hv.x); hp[1] = dup2(hv.y); hp[2] = dup2(hv.z); hp[3] = dup2(hv.w);
        #pragma unroll
        for (int i = 0; i < NH; i++) {
            ulonglong2 w = *(const ulonglong2*)(wb + k * (4 * H) + i * 4);
            #pragma unroll
            for (int b = 0; b < NB; b++) {
                aif[i][b] = fma2(w.x, hp[b], aif[i][b]);
                ago[i][b] = fma2(w.y, hp[b], ago[i][b]);
            }
        }
    }
}

// ---------------- activations + h store ----------------
template<int NH, int NB>
__device__ __forceinline__ void act_update(ull (&aif)[NH][NB], ull (&ago)[NH][NB],
                                           float (&cr)[NH][NB], float* __restrict__ Hw)
{
    #pragma unroll
    for (int i = 0; i < NH; i++) {
        float hn[NB];
        #pragma unroll
        for (int b = 0; b < NB; b++) {
            float2 sif = upk(aif[i][b]);
            float2 sgo = upk(ago[i][b]);
            float ig = sigm(sif.x);
            float fg = sigm(sif.y);
            float gg = tanh_(sgo.x);
            float og = sigm(sgo.y);
            float cn = fmaf(fg, cr[i][b], ig * gg);
            cr[i][b] = cn;
            hn[b] = og * tanh_(cn);
        }
        *(float4*)(Hw + i * BT) = make_float4(hn[0], hn[1], hn[2], hn[3]);
    }
}

// ---------------- one input-driven LSTM phase, group-local ----------------
template<int H, int NH, int NB, int HOFF, int T>
__device__ __forceinline__ void lstm_phase(float* __restrict__ S,
                                           const float* __restrict__ xsrc, int xstride,
                                           int B, int bbase, int g, int tid_g,
                                           int wsOff, int bpkOff, int ipkOff)
{
    constexpr int BG = GBT / NB;
    static_assert((H / NH) * BG == 128, "group thread map");
    int hg = tid_g / BG, bg = tid_g % BG;
    int j0 = hg * NH, bcol = g * GBT + bg * NB;

    float* Ws = S + wsOff;
    float* Cs = S + CS_OFF;
    float* H0 = S + HS_OFF;  float* H1 = H0 + 6144;
    ull*   X0 = (ull*)(S + XS_OFF); ull* X1 = X0 + 128;
    ull*   Bpk = (ull*)(S + bpkOff);
    ull*   Ipk = (ull*)(S + ipkOff);

    float cr[NH][NB];
    #pragma unroll
    for (int i = 0; i < NH; i++)
        #pragma unroll
        for (int b = 0; b < NB; b++) cr[i][b] = 0.0f;

    ull bif[NH], bgo[NH], wif0[NH], wif1[NH], wgo0[NH], wgo1[NH];
    #pragma unroll
    for (int i = 0; i < NH; i++) {
        bif[i]  = Bpk[(j0 + i) * 2 + 0];
        bgo[i]  = Bpk[(j0 + i) * 2 + 1];
        wif0[i] = Ipk[((j0 + i) * 2 + 0) * 2 + 0];
        wgo0[i] = Ipk[((j0 + i) * 2 + 0) * 2 + 1];
        wif1[i] = Ipk[((j0 + i) * 2 + 1) * 2 + 0];
        wgo1[i] = Ipk[((j0 + i) * 2 + 1) * 2 + 1];
    }

    // distributed x staging: lanes 0-3 of each warp stage 4 columns
    int laneg = tid_g & 31, ww = tid_g >> 5;
    bool stager = (laneg < 4);
    int  scol = g * GBT + ww * 4 + laneg;        // valid when stager
    int  bb = bbase + scol; if (bb >= B) bb = B - 1;
    if (stager) {
        float2 x = *(const float2*)&xsrc[(size_t)bb * xstride];
        X0[2 * scol + 0] = pk2(x.x, x.x);
        X0[2 * scol + 1] = pk2(x.y, x.y);
    }
    gbar(g);

    float* Hc = H0; float* Hn = H1;
    ull*   Xc = X0; ull*   Xn = X1;

    for (int t = 0; t < T; t++) {
        float2 xnv;
        bool st = stager && (t + 1 < T);
        if (st)   // prefetch next x early; LDG hides under gates_mm
            xnv = *(const float2*)&xsrc[(size_t)bb * xstride + (size_t)(t + 1) * 2];

        ull aif[NH][NB], ago[NH][NB];
        #pragma unroll
        for (int b = 0; b < NB; b++) {
            ull xa = Xc[2 * (bcol + b) + 0];
            ull xb = Xc[2 * (bcol + b) + 1];
            #pragma unroll
            for (int i = 0; i < NH; i++) {
                aif[i][b] = fma2(wif0[i], xa, fma2(wif1[i], xb, bif[i]));
                ago[i][b] = fma2(wgo0[i], xa, fma2(wgo1[i], xb, bgo[i]));
            }
        }
        gates_mm<H, NH, NB>(Ws, Hc + HOFF * BT + bcol, j0, aif, ago);
        act_update<NH, NB>(aif, ago, cr, Hn + (HOFF + j0) * BT + bcol);
        if (st) {
            Xn[2 * scol + 0] = pk2(xnv.x, xnv.x);
            Xn[2 * scol + 1] = pk2(xnv.y, xnv.y);
        }
        gbar(g);
        { float* tf = Hc; Hc = Hn; Hn = tf; }
        { ull*  tx = Xc; Xc = Xn; Xn = tx; }
    }
    // T even -> final h lands in H0 (decoder's read buffer)

    // stage final c for the decoder
    #pragma unroll
    for (int i = 0; i < NH; i++)
        #pragma unroll
        for (int b = 0; b < NB; b++)
            Cs[(HOFF + j0 + i) * BT + bcol + b] = cr[i][b];
}

// ---------------- main fused kernel ----------------
__global__ void __launch_bounds__(TPB, 1)
lstm_fused_kernel(const float* __restrict__ traj,   // [B,20,2]
                  const float* __restrict__ cl,     // [B,100,2]
                  const float* __restrict__ Wih_c, const float* __restrict__ Whh_c,
                  const float* __restrict__ bih_c, const float* __restrict__ bhh_c,
                  const float* __restrict__ Wih_e, const float* __restrict__ Whh_e,
                  const float* __restrict__ bih_e, const float* __restrict__ bhh_e,
                  const float* __restrict__ Wih_d, const float* __restrict__ Whh_d,
                  const float* __restrict__ bih_d, const float* __restrict__ bhh_d,
                  const float* __restrict__ W_emb, const float* __restrict__ b_emb,
                  float* __restrict__ out, int B)
{
    extern __shared__ float S[];
    int tid   = threadIdx.x;
    int bbase = blockIdx.x * BT;
    int g     = tid >> 7;        // group 0..3 (owns batch cols [16g, 16g+16))
    int tid_g = tid & 127;       // one warp per SMSP per group

    float*  H0   = S + HS_OFF;
    float*  Cs   = S + CS_OFF;
    ull*    BpkD = (ull*)(S + BPKD_OFF);
    float2* Wemb = (float2*)(S + WEMB_OFF);
    float2* Bemb = (float2*)(S + BEMB_OFF);

    // zero h buffer 0 (initial states for both phases; H1 is written before read)
    for (int s = tid; s < 6144; s += TPB) H0[s] = 0.0f;

    // stage BOTH phases' weights/biases up front (CTA-wide)
    load_W<32>(S + WS_C_OFF, Whh_c, nullptr, tid);
    load_W<64>(S + WS_E_OFF, Whh_e, nullptr, tid);
    load_bias<32>((ull*)(S + BPKC_OFF), bih_c, bhh_c, tid);
    load_ih<32>((ull*)(S + IPKC_OFF), Wih_c, tid);
    load_bias<64>((ull*)(S + BPKE_OFF), bih_e, bhh_e, tid);
    load_ih<64>((ull*)(S + IPKE_OFF), Wih_e, tid);
    __syncthreads();

    // anti-phase schedule across groups (plus free-running drift: no two
    // warps of one SMSP share a barrier)
    if (g & 1) {
        lstm_phase<64, 2, 4,  0,  20>(S, traj,  40, B, bbase, g, tid_g, WS_E_OFF, BPKE_OFF, IPKE_OFF);
        lstm_phase<32, 1, 4, 64, 100>(S, cl,   200, B, bbase, g, tid_g, WS_C_OFF, BPKC_OFF, IPKC_OFF);
    } else {
        lstm_phase<32, 1, 4, 64, 100>(S, cl,   200, B, bbase, g, tid_g, WS_C_OFF, BPKC_OFF, IPKC_OFF);
        lstm_phase<64, 2, 4,  0,  20>(S, traj,  40, B, bbase, g, tid_g, WS_E_OFF, BPKE_OFF, IPKE_OFF);
    }
    __syncthreads();

    // ---- decoder (H=96), x == h so Wih+Whh fold into one matrix ----
    {
        constexpr int NH = 3, NB = 4, BG = GBT / NB;   // 32 hidden groups x 4 batch groups
        int hg = tid_g / BG, bg = tid_g % BG;
        int j0 = hg * NH, bcol = g * GBT + bg * NB;

        // read c BEFORE load_W<96> clobbers the aliased Cs region
        float cr[NH][NB];
        #pragma unroll
        for (int i = 0; i < NH; i++)
            #pragma unroll
            for (int b = 0; b < NB; b++)
                cr[i][b] = Cs[(j0 + i) * BT + bcol + b];
        __syncthreads();

        load_W<96>(S + WS_D_OFF, Whh_d, Wih_d, tid);
        load_bias<96>(BpkD, bih_d, bhh_d, tid);
        for (int k = tid; k < 96; k += TPB) Wemb[k] = make_float2(W_emb[k], W_emb[96 + k]);
        if (tid == 0) *Bemb = make_float2(b_emb[0], b_emb[1]);
        __syncthreads();
        __nanosleep((unsigned)(g * 1100));  // seed per-group phase offset

        const float* Ws = S + WS_D_OFF;
        ull bif[NH], bgo[NH];
        #pragma unroll
        for (int i = 0; i < NH; i++) {
            bif[i] = BpkD[(j0 + i) * 2 + 0];
            bgo[i] = BpkD[(j0 + i) * 2 + 1];
        }

        float* Hc = S + HS_OFF;          // h0 = concat(enc, cent) in buffer 0
        float* Hn = S + HS_OFF + 6144;

        // distributed projection state
        int laneg = tid_g & 31, ww = tid_g >> 5;
        bool parter = (laneg < 16);
        int  pcol   = g * GBT + laneg;           // partial col (laneg<16)
        float2* Pp  = (float2*)(S + PP_OFF) + g * 128;   // [2 par][4 ww][16 col]
        bool summer = (tid_g < GBT);
        int  sb     = bbase + g * GBT + tid_g;   // summed batch row (tid_g<16)

        for (int t = 0; t < 30; t++) {
            ull aif[NH][NB], ago[NH][NB];
            #pragma unroll
            for (int i = 0; i < NH; i++)
                #pragma unroll
                for (int b = 0; b < NB; b++) { aif[i][b] = bif[i]; ago[i][b] = bgo[i]; }

            gates_mm<96, NH, NB>(Ws, Hc + bcol, j0, aif, ago);
            act_update<NH, NB>(aif, ago, cr, Hn + j0 * BT + bcol);
            gbar(g);                      // group's new h visible; prior partials visible

            // sum previous step's partials (16 threads, tiny)
            if (t > 0 && summer) {
                float2* Pq = Pp + ((t - 1) & 1) * 64;
                float2 a0 = Pq[0 * 16 + tid_g];
                float2 a1 = Pq[1 * 16 + tid_g];
                float2 a2 = Pq[2 * 16 + tid_g];
                float2 a3 = Pq[3 * 16 + tid_g];
                float2 acc = *Bemb;
                acc.x += (a0.x + a1.x) + (a2.x + a3.x);
                acc.y += (a0.y + a1.y) + (a2.y + a3.y);
                if (sb < B) *(float2*)&out[(size_t)(sb * 30 + (t - 1)) * 2] = acc;
            }

            // compute this step's projection partials: each warp takes a
            // 24-k slice over all 16 cols (lanes 0-15; conflict-free LDS)
            if (parter) {
                float2 acc = make_float2(0.0f, 0.0f);
                #pragma unroll 8
                for (int kk = 0; kk < 24; kk++) {
                    int k = ww * 24 + kk;
                    float  h = Hn[k * BT + pcol];
                    float2 we = Wemb[k];
                    acc.x = fmaf(h, we.x, acc.x);
                    acc.y = fmaf(h, we.y, acc.y);
                }
                Pp[(t & 1) * 64 + ww * 16 + laneg] = acc;
            }
            { float* tf = Hc; Hc = Hn; Hn = tf; }
        }

        // flush t = 29
        gbar(g);
        if (summer) {
            float2* Pq = Pp + (29 & 1) * 64;
            float2 a0 = Pq[0 * 16 + tid_g];
            float2 a1 = Pq[1 * 16 + tid_g];
            float2 a2 = Pq[2 * 16 + tid_g];
            float2 a3 = Pq[3 * 16 + tid_g];
            float2 acc = *Bemb;
            acc.x += (a0.x + a1.x) + (a2.x + a3.x);
            acc.y += (a0.y + a1.y) + (a2.y + a3.y);
            if (sb < B) *(float2*)&out[(size_t)(sb * 30 + 29) * 2] = acc;
        }
    }
}

extern "C" void kernel_launch(void* const* d_in, const int* in_sizes, int n_in,
                              void* d_out, int out_size)
{
    const float* traj  = (const float*)d_in[0];
    const float* cl    = (const float*)d_in[1];
    const float* Wih_c = (const float*)d_in[2];
    const float* Whh_c = (const float*)d_in[3];
    const float* bih_c = (const float*)d_in[4];
    const float* bhh_c = (const float*)d_in[5];
    const float* Wih_e = (const float*)d_in[6];
    const float* Whh_e = (const float*)d_in[7];
    const float* bih_e = (const float*)d_in[8];
    const float* bhh_e = (const float*)d_in[9];
    const float* Wih_d = (const float*)d_in[10];
    const float* Whh_d = (const float*)d_in[11];
    const float* bih_d = (const float*)d_in[12];
    const float* bhh_d = (const float*)d_in[13];
    const float* W_emb = (const float*)d_in[14];
    const float* b_emb = (const float*)d_in[15];

    int B = in_sizes[0] / 40;
    int grid = (B + BT - 1) / BT;

    cudaFuncSetAttribute(lstm_fused_kernel,
                         cudaFuncAttributeMaxDynamicSharedMemorySize, SMEM_BYTES);
    lstm_fused_kernel<<<grid, TPB, SMEM_BYTES>>>(
        traj, cl, Wih_c, Whh_c, bih_c, bhh_c,
        Wih_e, Whh_e, bih_e, bhh_e,
        Wih_d, Whh_d, bih_d, bhh_d,
        W_emb, b_emb, (float*)d_out, B);
}

// round 13
// speedup vs baseline: 1.5557x; 1.3180x over previous
#include <cuda_runtime.h>
#include <cuda_bf16.h>
#include <cstdint>

typedef unsigned long long ull;

// ---------------- packed f32x2 helpers ----------------
__device__ __forceinline__ ull pk2(float lo, float hi) {
    ull r; asm("mov.b64 %0, {%1, %2};" : "=l"(r) : "f"(lo), "f"(hi)); return r;
}
__device__ __forceinline__ ull dup2(float x) {
    ull r; asm("mov.b64 %0, {%1, %1};" : "=l"(r) : "f"(x)); return r;
}
__device__ __forceinline__ ull fma2(ull a, ull b, ull c) {
    ull d; asm("fma.rn.f32x2 %0, %1, %2, %3;" : "=l"(d) : "l"(a), "l"(b), "l"(c)); return d;
}
__device__ __forceinline__ float2 upk(ull a) {
    float lo, hi; asm("mov.b64 {%0, %1}, %2;" : "=f"(lo), "=f"(hi) : "l"(a));
    return make_float2(lo, hi);
}
__device__ __forceinline__ float tanh_(float x){
    float r; asm("tanh.approx.f32 %0, %1;" : "=f"(r) : "f"(x)); return r;
}
__device__ __forceinline__ float sigm(float x){
    return fmaf(0.5f, tanh_(0.5f * x), 0.5f);
}
// bf16x2 pack: lo half = a, hi half = b
__device__ __forceinline__ unsigned bf16x2_pack(float a, float b) {
    unsigned r;
    asm("cvt.rn.satfinite.bf16x2.f32 %0, %1, %2;" : "=r"(r) : "f"(b), "f"(a));
    return r;
}
// mma.sync m16n8k16 row.col f32.bf16.bf16.f32 (baseline PTX, sm_80+)
#define MMA_BF16(d, a0, a1, a2, a3, b0, b1) \
    asm volatile("mma.sync.aligned.m16n8k16.row.col.f32.bf16.bf16.f32 " \
        "{%0,%1,%2,%3}, {%4,%5,%6,%7}, {%8,%9}, {%0,%1,%2,%3};" \
        : "+f"((d)[0]), "+f"((d)[1]), "+f"((d)[2]), "+f"((d)[3]) \
        : "r"(a0), "r"(a1), "r"(a2), "r"(a3), "r"(b0), "r"(b1))

#define TPB  512
#define BT   64
#define GBT  16

__device__ __forceinline__ void gbar(int g) {
    asm volatile("bar.sync %0, %1;" :: "r"(g + 1), "r"(128) : "memory");
}

// ---------------- SMEM layout (float offsets) ----------------
// Phase regions (alive during cent/enc):
#define WS_C_OFF  0
#define WS_E_OFF  4096
#define CS_OFF    20480    // c staging [96][64]
#define HS_OFF    36864    // phase h: 2 x [96][64]
#define XS_OFF    49152
#define BPKC_OFF  49664
#define IPKC_OFF  49792
#define BPKE_OFF  50048
#define IPKE_OFF  50304
// Decoder regions (alive after handoff; alias phase regions):
#define WPK_OFF   0        // frag-packed W: 2 var x 6 kt x 48 nt x 32 lanes ull = 36864 f
#define HHIA_OFF  36864    // 64 x 49 bf16x2 words = 3136
#define HLOA_OFF  40000
#define HHIB_OFF  43136
#define HLOB_OFF  46272    // end 49408
#define PPART_OFF 50816    // 2 x [64 b][16 slot] float2 = 4096 f
#define BIASD_OFF 54912    // 384 f
#define WEMBD_OFF 55296    // 96 float2 = 192 f
#define BEMBD_OFF 55488    // 2 f
#define SMEM_FLOATS 55492
#define SMEM_BYTES  (SMEM_FLOATS * 4)

// ---------------- phase weight/bias staging ----------------
template<int H>
__device__ __forceinline__ void load_W(float* __restrict__ Ws,
                                       const float* __restrict__ Whh, int tid)
{
    constexpr int total = 4 * H * H;
    for (int s = tid; s < total; s += TPB) {
        int row = s / H;
        int k   = s - row * H;
        int g   = row / H;
        int j   = row - g * H;
        Ws[k * (4 * H) + j * 4 + g] = Whh[s];
    }
}
template<int H>
__device__ __forceinline__ void load_bias(ull* __restrict__ Bpk,
                                          const float* __restrict__ bih,
                                          const float* __restrict__ bhh, int tid)
{
    for (int j = tid; j < H; j += TPB) {
        Bpk[j * 2 + 0] = pk2(bih[j] + bhh[j],             bih[H + j] + bhh[H + j]);
        Bpk[j * 2 + 1] = pk2(bih[2*H + j] + bhh[2*H + j], bih[3*H + j] + bhh[3*H + j]);
    }
}
template<int H>
__device__ __forceinline__ void load_ih(ull* __restrict__ Ipk,
                                        const float* __restrict__ Wih, int tid)
{
    for (int t = tid; t < 2 * H; t += TPB) {
        int j = t >> 1, inp = t & 1;
        Ipk[(j * 2 + inp) * 2 + 0] = pk2(Wih[(0*H + j) * 2 + inp], Wih[(1*H + j) * 2 + inp]);
        Ipk[(j * 2 + inp) * 2 + 1] = pk2(Wih[(2*H + j) * 2 + inp], Wih[(3*H + j) * 2 + inp]);
    }
}

// ---------------- phase gate matmul (champion inner loop) ----------------
template<int H, int NH, int NB>
__device__ __forceinline__ void gates_mm(const float* __restrict__ Ws,
                                         const float* __restrict__ hbase, int j0,
                                         ull (&aif)[NH][NB], ull (&ago)[NH][NB])
{
    const float* wb = Ws + j0 * 4;
    #pragma unroll 4
    for (int k = 0; k < H; k++) {
        ull hp[NB];
        float4 hv = *(const float4*)(hbase + k * BT);
        hp[0] = dup2(hv.x); hp[1] = dup2(hv.y); hp[2] = dup2(hv.z); hp[3] = dup2(hv.w);
        #pragma unroll
        for (int i = 0; i < NH; i++) {
            ulonglong2 w = *(const ulonglong2*)(wb + k * (4 * H) + i * 4);
            #pragma unroll
            for (int b = 0; b < NB; b++) {
                aif[i][b] = fma2(w.x, hp[b], aif[i][b]);
                ago[i][b] = fma2(w.y, hp[b], ago[i][b]);
            }
        }
    }
}
template<int NH, int NB>
__device__ __forceinline__ void act_update(ull (&aif)[NH][NB], ull (&ago)[NH][NB],
                                           float (&cr)[NH][NB], float* __restrict__ Hw)
{
    #pragma unroll
    for (int i = 0; i < NH; i++) {
        float hn[NB];
        #pragma unroll
        for (int b = 0; b < NB; b++) {
            float2 sif = upk(aif[i][b]);
            float2 sgo = upk(ago[i][b]);
            float ig = sigm(sif.x);
            float fg = sigm(sif.y);
            float gg = tanh_(sgo.x);
            float og = sigm(sgo.y);
            float cn = fmaf(fg, cr[i][b], ig * gg);
            cr[i][b] = cn;
            hn[b] = og * tanh_(cn);
        }
        *(float4*)(Hw + i * BT) = make_float4(hn[0], hn[1], hn[2], hn[3]);
    }
}

// ---------------- one input-driven LSTM phase, group-local (R11 verbatim) ----
template<int H, int NH, int NB, int HOFF, int T>
__device__ __forceinline__ void lstm_phase(float* __restrict__ S,
                                           const float* __restrict__ xsrc, int xstride,
                                           int B, int bbase, int g, int tid_g,
                                           int wsOff, int bpkOff, int ipkOff)
{
    constexpr int BG = GBT / NB;
    static_assert((H / NH) * BG == 128, "group thread map");
    int hg = tid_g / BG, bg = tid_g % BG;
    int j0 = hg * NH, bcol = g * GBT + bg * NB;

    float* Ws = S + wsOff;
    float* Cs = S + CS_OFF;
    float* H0 = S + HS_OFF;  float* H1 = H0 + 6144;
    ull*   X0 = (ull*)(S + XS_OFF); ull* X1 = X0 + 128;
    ull*   Bpk = (ull*)(S + bpkOff);
    ull*   Ipk = (ull*)(S + ipkOff);

    float cr[NH][NB];
    #pragma unroll
    for (int i = 0; i < NH; i++)
        #pragma unroll
        for (int b = 0; b < NB; b++) cr[i][b] = 0.0f;

    ull bif[NH], bgo[NH], wif0[NH], wif1[NH], wgo0[NH], wgo1[NH];
    #pragma unroll
    for (int i = 0; i < NH; i++) {
        bif[i]  = Bpk[(j0 + i) * 2 + 0];
        bgo[i]  = Bpk[(j0 + i) * 2 + 1];
        wif0[i] = Ipk[((j0 + i) * 2 + 0) * 2 + 0];
        wgo0[i] = Ipk[((j0 + i) * 2 + 0) * 2 + 1];
        wif1[i] = Ipk[((j0 + i) * 2 + 1) * 2 + 0];
        wgo1[i] = Ipk[((j0 + i) * 2 + 1) * 2 + 1];
    }

    int laneg = tid_g & 31, ww = tid_g >> 5;
    bool stager = (laneg < 4);
    int  scol = g * GBT + ww * 4 + laneg;
    int  bb = bbase + scol; if (bb >= B) bb = B - 1;
    if (stager) {
        float2 x = *(const float2*)&xsrc[(size_t)bb * xstride];
        X0[2 * scol + 0] = pk2(x.x, x.x);
        X0[2 * scol + 1] = pk2(x.y, x.y);
    }
    gbar(g);

    float* Hc = H0; float* Hn = H1;
    ull*   Xc = X0; ull*   Xn = X1;

    for (int t = 0; t < T; t++) {
        float2 xnv;
        bool st = stager && (t + 1 < T);
        if (st)
            xnv = *(const float2*)&xsrc[(size_t)bb * xstride + (size_t)(t + 1) * 2];

        ull aif[NH][NB], ago[NH][NB];
        #pragma unroll
        for (int b = 0; b < NB; b++) {
            ull xa = Xc[2 * (bcol + b) + 0];
            ull xb = Xc[2 * (bcol + b) + 1];
            #pragma unroll
            for (int i = 0; i < NH; i++) {
                aif[i][b] = fma2(wif0[i], xa, fma2(wif1[i], xb, bif[i]));
                ago[i][b] = fma2(wgo0[i], xa, fma2(wgo1[i], xb, bgo[i]));
            }
        }
        gates_mm<H, NH, NB>(Ws, Hc + HOFF * BT + bcol, j0, aif, ago);
        act_update<NH, NB>(aif, ago, cr, Hn + (HOFF + j0) * BT + bcol);
        if (st) {
            Xn[2 * scol + 0] = pk2(xnv.x, xnv.x);
            Xn[2 * scol + 1] = pk2(xnv.y, xnv.y);
        }
        gbar(g);
        { float* tf = Hc; Hc = Hn; Hn = tf; }
        { ull*  tx = Xc; Xc = Xn; Xn = tx; }
    }

    #pragma unroll
    for (int i = 0; i < NH; i++)
        #pragma unroll
        for (int b = 0; b < NB; b++)
            Cs[(HOFF + j0 + i) * BT + bcol + b] = cr[i][b];
}

// ---------------- main fused kernel ----------------
__global__ void __launch_bounds__(TPB, 1)
lstm_fused_kernel(const float* __restrict__ traj,
                  const float* __restrict__ cl,
                  const float* __restrict__ Wih_c, const float* __restrict__ Whh_c,
                  const float* __restrict__ bih_c, const float* __restrict__ bhh_c,
                  const float* __restrict__ Wih_e, const float* __restrict__ Whh_e,
                  const float* __restrict__ bih_e, const float* __restrict__ bhh_e,
                  const float* __restrict__ Wih_d, const float* __restrict__ Whh_d,
                  const float* __restrict__ bih_d, const float* __restrict__ bhh_d,
                  const float* __restrict__ W_emb, const float* __restrict__ b_emb,
                  float* __restrict__ out, int B)
{
    extern __shared__ float S[];
    int tid   = threadIdx.x;
    int bbase = blockIdx.x * BT;
    int g     = tid >> 7;
    int tid_g = tid & 127;

    float* H0 = S + HS_OFF;

    for (int s = tid; s < 6144; s += TPB) H0[s] = 0.0f;

    load_W<32>(S + WS_C_OFF, Whh_c, tid);
    load_W<64>(S + WS_E_OFF, Whh_e, tid);
    load_bias<32>((ull*)(S + BPKC_OFF), bih_c, bhh_c, tid);
    load_ih<32>((ull*)(S + IPKC_OFF), Wih_c, tid);
    load_bias<64>((ull*)(S + BPKE_OFF), bih_e, bhh_e, tid);
    load_ih<64>((ull*)(S + IPKE_OFF), Wih_e, tid);
    __syncthreads();

    if (g & 1) {
        lstm_phase<64, 2, 4,  0,  20>(S, traj,  40, B, bbase, g, tid_g, WS_E_OFF, BPKE_OFF, IPKE_OFF);
        lstm_phase<32, 1, 4, 64, 100>(S, cl,   200, B, bbase, g, tid_g, WS_C_OFF, BPKC_OFF, IPKC_OFF);
    } else {
        lstm_phase<32, 1, 4, 64, 100>(S, cl,   200, B, bbase, g, tid_g, WS_C_OFF, BPKC_OFF, IPKC_OFF);
        lstm_phase<64, 2, 4,  0,  20>(S, traj,  40, B, bbase, g, tid_g, WS_E_OFF, BPKE_OFF, IPKE_OFF);
    }
    __syncthreads();

    // ================= decoder via mma.sync (split-bf16, 3 passes) ==========
    {
        int w    = tid >> 5, lane = tid & 31;
        int mt   = w & 3;            // m-tile: batch rows [mt*16, mt*16+16)
        int wg   = w >> 2;           // n-slice: 24 gate-cols per gate block
        int lq   = lane >> 2;        // lane/4
        int lr   = lane & 3;         // lane%4
        int brow = mt * 16 + lq;     // D-frag row (and +8)
        int jb   = wg * 24 + lr * 2; // D-frag col base: j = jb + nt*8 + dc

        // ---- read c (D-frag layout) + h0 pairs into regs BEFORE aliasing ----
        float c[3][4];
        #pragma unroll
        for (int nt = 0; nt < 3; nt++)
            #pragma unroll
            for (int idx = 0; idx < 4; idx++) {
                int j = jb + nt * 8 + (idx & 1);
                int b = brow + (idx >> 1) * 8;
                c[nt][idx] = S[CS_OFF + j * 64 + b];
            }
        float h0a[6], h0b[6];
        #pragma unroll
        for (int s = 0; s < 6; s++) {
            int p = tid + s * TPB;          // pair index 0..3071
            int b = p / 48, j2 = p % 48;
            h0a[s] = S[HS_OFF + (2 * j2) * 64 + b];
            h0b[s] = S[HS_OFF + (2 * j2 + 1) * 64 + b];
        }
        __syncthreads();

        // ---- stage frag-packed W (hi/lo), bias, Wemb; write h0 hi/lo ----
        ull* Wp = (ull*)(S + WPK_OFF);
        for (int s = tid; s < 6 * 48 * 32; s += TPB) {
            int ln = s & 31;
            int ntile = (s >> 5) % 48;
            int kt = (s >> 5) / 48;
            int n  = ntile * 8 + (ln >> 2);
            int k0 = kt * 16 + (ln & 3) * 2;
            const float* wi = Wih_d + n * 96;
            const float* wh = Whh_d + n * 96;
            float v00 = wi[k0]     + wh[k0];
            float v01 = wi[k0 + 1] + wh[k0 + 1];
            float v10 = wi[k0 + 8] + wh[k0 + 8];
            float v11 = wi[k0 + 9] + wh[k0 + 9];
            unsigned p0 = bf16x2_pack(v00, v01);
            unsigned p1 = bf16x2_pack(v10, v11);
            float r00 = __uint_as_float(p0 << 16);
            float r01 = __uint_as_float(p0 & 0xffff0000u);
            float r10 = __uint_as_float(p1 << 16);
            float r11 = __uint_as_float(p1 & 0xffff0000u);
            unsigned q0 = bf16x2_pack(v00 - r00, v01 - r01);
            unsigned q1 = bf16x2_pack(v10 - r10, v11 - r11);
            Wp[((0 + kt) * 48 + ntile) * 32 + ln] = (ull)p0 | ((ull)p1 << 32);
            Wp[((6 + kt) * 48 + ntile) * 32 + ln] = (ull)q0 | ((ull)q1 << 32);
        }
        float* biasd = S + BIASD_OFF;
        for (int j = tid; j < 384; j += TPB) biasd[j] = bih_d[j] + bhh_d[j];
        float2* Wemb = (float2*)(S + WEMBD_OFF);
        for (int k = tid; k < 96; k += TPB) Wemb[k] = make_float2(W_emb[k], W_emb[96 + k]);
        float2* Bemb = (float2*)(S + BEMBD_OFF);
        if (tid == 0) *Bemb = make_float2(b_emb[0], b_emb[1]);

        unsigned* HhiA = (unsigned*)(S + HHIA_OFF);
        unsigned* HloA = (unsigned*)(S + HLOA_OFF);
        unsigned* HhiB = (unsigned*)(S + HHIB_OFF);
        unsigned* HloB = (unsigned*)(S + HLOB_OFF);
        #pragma unroll
        for (int s = 0; s < 6; s++) {
            int p = tid + s * TPB;
            int b = p / 48, j2 = p % 48;
            unsigned ph = bf16x2_pack(h0a[s], h0b[s]);
            float r0 = __uint_as_float(ph << 16);
            float r1 = __uint_as_float(ph & 0xffff0000u);
            unsigned pl = bf16x2_pack(h0a[s] - r0, h0b[s] - r1);
            HhiA[b * 49 + j2] = ph;
            HloA[b * 49 + j2] = pl;
        }
        __syncthreads();

        unsigned* HhiC = HhiA; unsigned* HloC = HloA;
        unsigned* HhiN = HhiB; unsigned* HloN = HloB;
        float2* Ppart = (float2*)(S + PPART_OFF);   // [2 par][64 b][16 slot]
        int slot = wg * 4 + lr;
        int abase = brow * 49 + lr;                 // A-frag word base

        for (int t = 0; t < 30; t++) {
            float acc[12][4];
            #pragma unroll
            for (int q = 0; q < 12; q++)
                #pragma unroll
                for (int e = 0; e < 4; e++) acc[q][e] = 0.0f;

            // 3 passes: Ahi*Whi, Ahi*Wlo, Alo*Whi
            #pragma unroll
            for (int pass = 0; pass < 3; pass++) {
                const unsigned* Av = (pass == 2) ? HloC : HhiC;
                const ull* Wv = Wp + (pass == 1 ? 6 * 48 * 32 : 0);
                #pragma unroll
                for (int kt = 0; kt < 6; kt++) {
                    unsigned a0 = Av[abase + kt * 8];
                    unsigned a1 = Av[abase + kt * 8 + 392];       // +8 rows
                    unsigned a2 = Av[abase + kt * 8 + 4];         // k+8
                    unsigned a3 = Av[abase + kt * 8 + 396];
                    #pragma unroll
                    for (int G = 0; G < 4; G++)
                        #pragma unroll
                        for (int nt = 0; nt < 3; nt++) {
                            int ntile = G * 12 + wg * 3 + nt;
                            ull bv = Wv[(kt * 48 + ntile) * 32 + lane];
                            unsigned b0 = (unsigned)bv;
                            unsigned b1 = (unsigned)(bv >> 32);
                            MMA_BF16(acc[G * 3 + nt], a0, a1, a2, a3, b0, b1);
                        }
                }
            }

            // epilogue: activations, c update, h, projection partials
            float2 proj0 = make_float2(0.0f, 0.0f);
            float2 proj1 = make_float2(0.0f, 0.0f);
            #pragma unroll
            for (int nt = 0; nt < 3; nt++) {
                float h[4];
                #pragma unroll
                for (int idx = 0; idx < 4; idx++) {
                    int j = jb + nt * 8 + (idx & 1);
                    float gi = acc[0 * 3 + nt][idx] + biasd[j];
                    float gf = acc[1 * 3 + nt][idx] + biasd[96 + j];
                    float gg = acc[2 * 3 + nt][idx] + biasd[192 + j];
                    float go = acc[3 * 3 + nt][idx] + biasd[288 + j];
                    float fi = sigm(gi);
                    float ff = sigm(gf);
                    float fg = tanh_(gg);
                    float fo = sigm(go);
                    float cn = fmaf(ff, c[nt][idx], fi * fg);
                    c[nt][idx] = cn;
                    h[idx] = fo * tanh_(cn);
                    float2 we = Wemb[j];
                    if (idx < 2) {
                        proj0.x = fmaf(h[idx], we.x, proj0.x);
                        proj0.y = fmaf(h[idx], we.y, proj0.y);
                    } else {
                        proj1.x = fmaf(h[idx], we.x, proj1.x);
                        proj1.y = fmaf(h[idx], we.y, proj1.y);
                    }
                }
                // pack + store new h (rows brow, brow+8; col pair jb/2 + nt*4)
                int pidx = (jb >> 1) + nt * 4;
                unsigned ph0 = bf16x2_pack(h[0], h[1]);
                float s0 = __uint_as_float(ph0 << 16);
                float s1 = __uint_as_float(ph0 & 0xffff0000u);
                unsigned pl0 = bf16x2_pack(h[0] - s0, h[1] - s1);
                unsigned ph1 = bf16x2_pack(h[2], h[3]);
                float s2 = __uint_as_float(ph1 << 16);
                float s3 = __uint_as_float(ph1 & 0xffff0000u);
                unsigned pl1 = bf16x2_pack(h[2] - s2, h[3] - s3);
                HhiN[brow * 49 + pidx] = ph0;
                HloN[brow * 49 + pidx] = pl0;
                HhiN[(brow + 8) * 49 + pidx] = ph1;
                HloN[(brow + 8) * 49 + pidx] = pl1;
            }
            Ppart[(t & 1) * 1024 + brow * 16 + slot] = proj0;
            Ppart[(t & 1) * 1024 + (brow + 8) * 16 + slot] = proj1;

            __syncthreads();   // new h + partials visible

            // reduce + emit output for step t (64 threads; overlaps next mma)
            if (tid < BT) {
                const float4* Pq = (const float4*)(Ppart + (t & 1) * 1024 + tid * 16);
                float2 a = *Bemb;
                #pragma unroll
                for (int q = 0; q < 8; q++) {
                    float4 v = Pq[q];
                    a.x += v.x + v.z;
                    a.y += v.y + v.w;
                }
                int bgl = bbase + tid;
                if (bgl < B) *(float2*)&out[(size_t)(bgl * 30 + t) * 2] = a;
            }
            { unsigned* tp = HhiC; HhiC = HhiN; HhiN = tp; }
            { unsigned* tp = HloC; HloC = HloN; HloN = tp; }
        }
    }
}

extern "C" void kernel_launch(void* const* d_in, const int* in_sizes, int n_in,
                              void* d_out, int out_size)
{
    const float* traj  = (const float*)d_in[0];
    const float* cl    = (const float*)d_in[1];
    const float* Wih_c = (const float*)d_in[2];
    const float* Whh_c = (const float*)d_in[3];
    const float* bih_c = (const float*)d_in[4];
    const float* bhh_c = (const float*)d_in[5];
    const float* Wih_e = (const float*)d_in[6];
    const float* Whh_e = (const float*)d_in[7];
    const float* bih_e = (const float*)d_in[8];
    const float* bhh_e = (const float*)d_in[9];
    const float* Wih_d = (const float*)d_in[10];
    const float* Whh_d = (const float*)d_in[11];
    const float* bih_d = (const float*)d_in[12];
    const float* bhh_d = (const float*)d_in[13];
    const float* W_emb = (const float*)d_in[14];
    const float* b_emb = (const float*)d_in[15];

    int B = in_sizes[0] / 40;
    int grid = (B + BT - 1) / BT;

    cudaFuncSetAttribute(lstm_fused_kernel,
                         cudaFuncAttributeMaxDynamicSharedMemorySize, SMEM_BYTES);
    lstm_fused_kernel<<<grid, TPB, SMEM_BYTES>>>(
        traj, cl, Wih_c, Whh_c, bih_c, bhh_c,
        Wih_e, Whh_e, bih_e, bhh_e,
        Wih_d, Whh_d, bih_d, bhh_d,
        W_emb, b_emb, (float*)d_out, B);
}

// round 14
// speedup vs baseline: 2.1348x; 1.3723x over previous
#include <cuda_runtime.h>
#include <cuda_bf16.h>
#include <cstdint>

typedef unsigned long long ull;

#define TPB  512
#define BT   64

// ---------------- activations (HW tanh, 1 MUFU each) ----------------
__device__ __forceinline__ float tanh_(float x){
    float r; asm("tanh.approx.f32 %0, %1;" : "=f"(r) : "f"(x)); return r;
}
__device__ __forceinline__ float sigm(float x){
    return fmaf(0.5f, tanh_(0.5f * x), 0.5f);
}
// bf16x2 pack: lo half = a, hi half = b
__device__ __forceinline__ unsigned bf16x2_pack(float a, float b) {
    unsigned r;
    asm("cvt.rn.satfinite.bf16x2.f32 %0, %1, %2;" : "=r"(r) : "f"(b), "f"(a));
    return r;
}
// split (a,b) into bf16x2 hi + bf16x2 lo (residual)
__device__ __forceinline__ void split2(float a, float b, unsigned& hi, unsigned& lo) {
    hi = bf16x2_pack(a, b);
    float r0 = __uint_as_float(hi << 16);
    float r1 = __uint_as_float(hi & 0xffff0000u);
    lo = bf16x2_pack(a - r0, b - r1);
}
// mma.sync m16n8k16 row.col f32.bf16.bf16.f32 (baseline PTX, sm_80+)
#define MMA_BF16(d, a0, a1, a2, a3, b0, b1) \
    asm volatile("mma.sync.aligned.m16n8k16.row.col.f32.bf16.bf16.f32 " \
        "{%0,%1,%2,%3}, {%4,%5,%6,%7}, {%8,%9}, {%0,%1,%2,%3};" \
        : "+f"((d)[0]), "+f"((d)[1]), "+f"((d)[2]), "+f"((d)[3]) \
        : "r"(a0), "r"(a1), "r"(a2), "r"(a3), "r"(b0), "r"(b1))

// ---------------- SMEM layout (float offsets) ----------------
#define WPC_OFF   0        // cent packed W: 2var x 3kt x 16nt x 32 ull = 6144 f
#define WPE_OFF   6144     // enc  packed W: 2var x 5kt x 32nt x 32 ull = 20480 f
#define CS_OFF    26624    // c staging [96][64] = 6144 f
#define PHB_OFF   32768    // phase h buf (hi|lo contiguous), max enc 2*64*40 = 5120 f
#define DHA_HI    37888    // decoder h A hi: 64*49 = 3136 f
#define DHA_LO    41024
#define DHB_HI    44160
#define DHB_LO    47296
#define WPD_OFF   0        // decoder packed W (36864 f) — staged AFTER phases
#define PPART_OFF 50432    // proj partials: 2 x [64][16] float2 = 4096 f
#define BIASD_OFF 54528    // 384 f
#define WEMBD_OFF 54912    // 96 float2
#define BEMBD_OFF 55104    // 1 float2
#define BIASC_OFF 55106    // 128 f
#define BIASE_OFF 55234    // 256 f
#define SMEM_FLOATS 55490
#define SMEM_BYTES  (SMEM_FLOATS * 4)

// ---------------- phase weight packing (Whh + x-kt holding Wih) ----------------
// Layout: Wp[(var*KTX + kt)*NT*32 + ntile*32 + lane], ntile covers gate rows
// [ntile*8, ntile*8+8); kt<KT are h K-tiles, kt==KT is the x K-tile where only
// k-local 0,1 are nonzero (= Wih columns 0,1).
template<int H>
__device__ __forceinline__ void stage_Wphase(ull* __restrict__ Wp,
                                             const float* __restrict__ Whh,
                                             const float* __restrict__ Wih, int tid)
{
    constexpr int KT = H / 16, KTX = KT + 1, NT = (4 * H) / 8;
    for (int s = tid; s < KTX * NT * 32; s += TPB) {
        int ln = s & 31;
        int ntile = (s >> 5) % NT;
        int kt = (s >> 5) / NT;
        int n = ntile * 8 + (ln >> 2);
        int kl = (ln & 3) * 2;
        float v00, v01, v10, v11;
        if (kt < KT) {
            const float* r = Whh + n * H + kt * 16 + kl;
            v00 = r[0]; v01 = r[1]; v10 = r[8]; v11 = r[9];
        } else {
            v00 = (kl == 0) ? Wih[n * 2 + 0] : 0.0f;
            v01 = (kl == 0) ? Wih[n * 2 + 1] : 0.0f;
            v10 = 0.0f; v11 = 0.0f;
        }
        unsigned h0, l0, h1, l1;
        split2(v00, v01, h0, l0);
        split2(v10, v11, h1, l1);
        Wp[(kt * NT + ntile) * 32 + ln]         = (ull)h0 | ((ull)h1 << 32);
        Wp[((KTX + kt) * NT + ntile) * 32 + ln] = (ull)l0 | ((ull)l1 << 32);
    }
}

// ---------------- one input-driven LSTM phase via mma.sync ----------------
// Full-CTA; h stored as bf16x2 hi/lo words [64 rows][STR], x folded into the
// extra K-tile (word KT*8). Final h copied into the decoder A buffer at
// dstWordOff; final c staged into Cs rows [csHOFF, csHOFF+H).
template<int H, int T>
__device__ __forceinline__ void phase_mma(float* __restrict__ S,
                                          const float* __restrict__ xsrc, int xstride,
                                          int B, int bbase, int tid,
                                          int wpkOff, int biasOff,
                                          int csHOFF, int dstWordOff)
{
    constexpr int KT  = H / 16;
    constexpr int KTX = KT + 1;
    constexpr int NT  = (4 * H) / 8;
    constexpr int NTG = H / 32;          // ntiles per gate per warp
    constexpr int STR = H / 2 + 8;       // words per row (h words + x kt block)
    constexpr int BUFW = 64 * STR;

    int w = tid >> 5, lane = tid & 31;
    int mt = w & 3, wg = w >> 2;
    int lq = lane >> 2, lr = lane & 3;
    int brow = mt * 16 + lq;

    unsigned* Hhi = (unsigned*)(S + PHB_OFF);
    unsigned* Hlo = Hhi + BUFW;
    const ull* Wp = (const ull*)(S + wpkOff);
    const float* biasPh = S + biasOff;

    // zero buffers (h words start 0; x-kt pad words stay 0 forever)
    for (int s = tid; s < 2 * BUFW; s += TPB) Hhi[s] = 0u;

    // per-thread bias regs: bR[gate][nt][jpair]
    float bR[4][NTG][2];
    #pragma unroll
    for (int G = 0; G < 4; G++)
        #pragma unroll
        for (int nt = 0; nt < NTG; nt++) {
            int j = (wg * NTG + nt) * 8 + lr * 2;
            bR[G][nt][0] = biasPh[G * H + j];
            bR[G][nt][1] = biasPh[G * H + j + 1];
        }

    float c[NTG][4];
    #pragma unroll
    for (int nt = 0; nt < NTG; nt++)
        #pragma unroll
        for (int e = 0; e < 4; e++) c[nt][e] = 0.0f;

    int bx = bbase + tid; if (bx >= B) bx = B - 1;
    __syncthreads();                        // zeros done
    if (tid < 64) {                         // stage x(0)
        float2 x = *(const float2*)&xsrc[(size_t)bx * xstride];
        unsigned xh, xl; split2(x.x, x.y, xh, xl);
        Hhi[tid * STR + KT * 8] = xh;
        Hlo[tid * STR + KT * 8] = xl;
    }
    __syncthreads();

    int abase = brow * STR + lr;

    for (int t = 0; t < T; t++) {
        float2 xn;
        bool st = (tid < 64) && (t + 1 < T);
        if (st)
            xn = *(const float2*)&xsrc[(size_t)bx * xstride + (size_t)(t + 1) * 2];

        float acc[4 * NTG][4];
        #pragma unroll
        for (int q = 0; q < 4 * NTG; q++)
            #pragma unroll
            for (int e = 0; e < 4; e++) acc[q][e] = 0.0f;

        #pragma unroll
        for (int kt = 0; kt < KTX; kt++) {
            unsigned ah0 = Hhi[abase + kt * 8];
            unsigned ah1 = Hhi[abase + kt * 8 + 8 * STR];
            unsigned ah2 = Hhi[abase + kt * 8 + 4];
            unsigned ah3 = Hhi[abase + kt * 8 + 8 * STR + 4];
            unsigned al0 = Hlo[abase + kt * 8];
            unsigned al1 = Hlo[abase + kt * 8 + 8 * STR];
            unsigned al2 = Hlo[abase + kt * 8 + 4];
            unsigned al3 = Hlo[abase + kt * 8 + 8 * STR + 4];
            #pragma unroll
            for (int G = 0; G < 4; G++)
                #pragma unroll
                for (int nt = 0; nt < NTG; nt++) {
                    int ntile = G * (H / 8) + wg * NTG + nt;
                    ull whi = Wp[(kt * NT + ntile) * 32 + lane];
                    unsigned w0 = (unsigned)whi, w1 = (unsigned)(whi >> 32);
                    MMA_BF16(acc[G * NTG + nt], ah0, ah1, ah2, ah3, w0, w1);
                    MMA_BF16(acc[G * NTG + nt], al0, al1, al2, al3, w0, w1);
                    ull wlo = Wp[((KTX + kt) * NT + ntile) * 32 + lane];
                    unsigned q0 = (unsigned)wlo, q1 = (unsigned)(wlo >> 32);
                    MMA_BF16(acc[G * NTG + nt], ah0, ah1, ah2, ah3, q0, q1);
                }
        }
        __syncthreads();                   // all h/x reads done

        #pragma unroll
        for (int nt = 0; nt < NTG; nt++) {
            float h[4];
            #pragma unroll
            for (int idx = 0; idx < 4; idx++) {
                int p = idx & 1;
                float gi = acc[0 * NTG + nt][idx] + bR[0][nt][p];
                float gf = acc[1 * NTG + nt][idx] + bR[1][nt][p];
                float gg = acc[2 * NTG + nt][idx] + bR[2][nt][p];
                float go = acc[3 * NTG + nt][idx] + bR[3][nt][p];
                float fi = sigm(gi);
                float ff = sigm(gf);
                float fg = tanh_(gg);
                float fo = sigm(go);
                float cn = fmaf(ff, c[nt][idx], fi * fg);
                c[nt][idx] = cn;
                h[idx] = fo * tanh_(cn);
            }
            int jw = (wg * NTG + nt) * 4 + lr;
            unsigned ph0, pl0, ph1, pl1;
            split2(h[0], h[1], ph0, pl0);
            split2(h[2], h[3], ph1, pl1);
            Hhi[brow * STR + jw] = ph0;        Hlo[brow * STR + jw] = pl0;
            Hhi[(brow + 8) * STR + jw] = ph1;  Hlo[(brow + 8) * STR + jw] = pl1;
        }
        if (st) {
            unsigned xh, xl; split2(xn.x, xn.y, xh, xl);
            Hhi[tid * STR + KT * 8] = xh;
            Hlo[tid * STR + KT * 8] = xl;
        }
        __syncthreads();                   // new h + x visible
    }

    // stage final c into Cs
    #pragma unroll
    for (int nt = 0; nt < NTG; nt++)
        #pragma unroll
        for (int idx = 0; idx < 4; idx++) {
            int j = (wg * NTG + nt) * 8 + lr * 2 + (idx & 1);
            int b = brow + (idx >> 1) * 8;
            S[CS_OFF + (csHOFF + j) * 64 + b] = c[nt][idx];
        }

    // copy final h into decoder A buffer (disjoint regions; no race)
    constexpr int CW = 64 * (H / 2);
    unsigned* DHhi = (unsigned*)(S + DHA_HI);
    unsigned* DHlo = (unsigned*)(S + DHA_LO);
    for (int idx = tid; idx < CW; idx += TPB) {
        int row = idx / (H / 2), ww = idx % (H / 2);
        DHhi[row * 49 + dstWordOff + ww] = Hhi[row * STR + ww];
        DHlo[row * 49 + dstWordOff + ww] = Hlo[row * STR + ww];
    }
}

// ---------------- main fused kernel ----------------
__global__ void __launch_bounds__(TPB, 1)
lstm_fused_kernel(const float* __restrict__ traj,   // [B,20,2]
                  const float* __restrict__ cl,     // [B,100,2]
                  const float* __restrict__ Wih_c, const float* __restrict__ Whh_c,
                  const float* __restrict__ bih_c, const float* __restrict__ bhh_c,
                  const float* __restrict__ Wih_e, const float* __restrict__ Whh_e,
                  const float* __restrict__ bih_e, const float* __restrict__ bhh_e,
                  const float* __restrict__ Wih_d, const float* __restrict__ Whh_d,
                  const float* __restrict__ bih_d, const float* __restrict__ bhh_d,
                  const float* __restrict__ W_emb, const float* __restrict__ b_emb,
                  float* __restrict__ out, int B)
{
    extern __shared__ float S[];
    int tid   = threadIdx.x;
    int bbase = blockIdx.x * BT;

    // ---- stage phase weights / biases ----
    stage_Wphase<32>((ull*)(S + WPC_OFF), Whh_c, Wih_c, tid);
    stage_Wphase<64>((ull*)(S + WPE_OFF), Whh_e, Wih_e, tid);
    for (int j = tid; j < 128; j += TPB) S[BIASC_OFF + j] = bih_c[j] + bhh_c[j];
    for (int j = tid; j < 256; j += TPB) S[BIASE_OFF + j] = bih_e[j] + bhh_e[j];
    __syncthreads();

    // ---- phase 1: centerline LSTM (H=32, 100 steps) -> dec words 32..47, c rows 64..95
    phase_mma<32, 100>(S, cl, 200, B, bbase, tid, WPC_OFF, BIASC_OFF, 64, 32);
    __syncthreads();

    // ---- phase 2: encoder LSTM (H=64, 20 steps) -> dec words 0..31, c rows 0..63
    phase_mma<64, 20>(S, traj, 40, B, bbase, tid, WPE_OFF, BIASE_OFF, 0, 0);
    __syncthreads();

    // ================= decoder via mma.sync (split-bf16) =====================
    {
        int w    = tid >> 5, lane = tid & 31;
        int mt   = w & 3;
        int wg   = w >> 2;
        int lq   = lane >> 2;
        int lr   = lane & 3;
        int brow = mt * 16 + lq;
        int jb   = wg * 24 + lr * 2;

        // read c (D-frag layout) BEFORE decoder W staging clobbers Cs
        float c[3][4];
        #pragma unroll
        for (int nt = 0; nt < 3; nt++)
            #pragma unroll
            for (int idx = 0; idx < 4; idx++) {
                int j = jb + nt * 8 + (idx & 1);
                int b = brow + (idx >> 1) * 8;
                c[nt][idx] = S[CS_OFF + j * 64 + b];
            }
        __syncthreads();

        // stage frag-packed decoder W (hi/lo), bias, Wemb
        ull* Wp = (ull*)(S + WPD_OFF);
        for (int s = tid; s < 6 * 48 * 32; s += TPB) {
            int ln = s & 31;
            int ntile = (s >> 5) % 48;
            int kt = (s >> 5) / 48;
            int n  = ntile * 8 + (ln >> 2);
            int k0 = kt * 16 + (ln & 3) * 2;
            const float* wi = Wih_d + n * 96;
            const float* wh = Whh_d + n * 96;
            float v00 = wi[k0]     + wh[k0];
            float v01 = wi[k0 + 1] + wh[k0 + 1];
            float v10 = wi[k0 + 8] + wh[k0 + 8];
            float v11 = wi[k0 + 9] + wh[k0 + 9];
            unsigned h0, l0, h1, l1;
            split2(v00, v01, h0, l0);
            split2(v10, v11, h1, l1);
            Wp[(kt * 48 + ntile) * 32 + ln]       = (ull)h0 | ((ull)h1 << 32);
            Wp[((6 + kt) * 48 + ntile) * 32 + ln] = (ull)l0 | ((ull)l1 << 32);
        }
        float* biasd = S + BIASD_OFF;
        for (int j = tid; j < 384; j += TPB) biasd[j] = bih_d[j] + bhh_d[j];
        float2* Wemb = (float2*)(S + WEMBD_OFF);
        for (int k = tid; k < 96; k += TPB) Wemb[k] = make_float2(W_emb[k], W_emb[96 + k]);
        float2* Bemb = (float2*)(S + BEMBD_OFF);
        if (tid == 0) *Bemb = make_float2(b_emb[0], b_emb[1]);
        __syncthreads();

        unsigned* HhiC = (unsigned*)(S + DHA_HI);
        unsigned* HloC = (unsigned*)(S + DHA_LO);
        unsigned* HhiN = (unsigned*)(S + DHB_HI);
        unsigned* HloN = (unsigned*)(S + DHB_LO);
        float2* Ppart = (float2*)(S + PPART_OFF);   // [2 par][64 b][16 slot]
        int slot = wg * 4 + lr;
        int abase = brow * 49 + lr;

        for (int t = 0; t < 30; t++) {
            float acc[12][4];
            #pragma unroll
            for (int q = 0; q < 12; q++)
                #pragma unroll
                for (int e = 0; e < 4; e++) acc[q][e] = 0.0f;

            // per kt: load A hi/lo once; reuse Whi for both Ahi and Alo passes
            #pragma unroll
            for (int kt = 0; kt < 6; kt++) {
                unsigned ah0 = HhiC[abase + kt * 8];
                unsigned ah1 = HhiC[abase + kt * 8 + 392];
                unsigned ah2 = HhiC[abase + kt * 8 + 4];
                unsigned ah3 = HhiC[abase + kt * 8 + 396];
                unsigned al0 = HloC[abase + kt * 8];
                unsigned al1 = HloC[abase + kt * 8 + 392];
                unsigned al2 = HloC[abase + kt * 8 + 4];
                unsigned al3 = HloC[abase + kt * 8 + 396];
                #pragma unroll
                for (int G = 0; G < 4; G++)
                    #pragma unroll
                    for (int nt = 0; nt < 3; nt++) {
                        int ntile = G * 12 + wg * 3 + nt;
                        ull whi = Wp[(kt * 48 + ntile) * 32 + lane];
                        unsigned w0 = (unsigned)whi, w1 = (unsigned)(whi >> 32);
                        MMA_BF16(acc[G * 3 + nt], ah0, ah1, ah2, ah3, w0, w1);
                        MMA_BF16(acc[G * 3 + nt], al0, al1, al2, al3, w0, w1);
                        ull wlo = Wp[((6 + kt) * 48 + ntile) * 32 + lane];
                        unsigned q0 = (unsigned)wlo, q1 = (unsigned)(wlo >> 32);
                        MMA_BF16(acc[G * 3 + nt], ah0, ah1, ah2, ah3, q0, q1);
                    }
            }

            // epilogue: activations, c update, h, projection partials
            float2 proj0 = make_float2(0.0f, 0.0f);
            float2 proj1 = make_float2(0.0f, 0.0f);
            #pragma unroll
            for (int nt = 0; nt < 3; nt++) {
                float h[4];
                #pragma unroll
                for (int idx = 0; idx < 4; idx++) {
                    int j = jb + nt * 8 + (idx & 1);
                    float gi = acc[0 * 3 + nt][idx] + biasd[j];
                    float gf = acc[1 * 3 + nt][idx] + biasd[96 + j];
                    float gg = acc[2 * 3 + nt][idx] + biasd[192 + j];
                    float go = acc[3 * 3 + nt][idx] + biasd[288 + j];
                    float fi = sigm(gi);
                    float ff = sigm(gf);
                    float fg = tanh_(gg);
                    float fo = sigm(go);
                    float cn = fmaf(ff, c[nt][idx], fi * fg);
                    c[nt][idx] = cn;
                    h[idx] = fo * tanh_(cn);
                    float2 we = Wemb[j];
                    if (idx < 2) {
                        proj0.x = fmaf(h[idx], we.x, proj0.x);
                        proj0.y = fmaf(h[idx], we.y, proj0.y);
                    } else {
                        proj1.x = fmaf(h[idx], we.x, proj1.x);
                        proj1.y = fmaf(h[idx], we.y, proj1.y);
                    }
                }
                int pidx = (jb >> 1) + nt * 4;
                unsigned ph0, pl0, ph1, pl1;
                split2(h[0], h[1], ph0, pl0);
                split2(h[2], h[3], ph1, pl1);
                HhiN[brow * 49 + pidx] = ph0;        HloN[brow * 49 + pidx] = pl0;
                HhiN[(brow + 8) * 49 + pidx] = ph1;  HloN[(brow + 8) * 49 + pidx] = pl1;
            }
            Ppart[(t & 1) * 1024 + brow * 16 + slot] = proj0;
            Ppart[(t & 1) * 1024 + (brow + 8) * 16 + slot] = proj1;

            __syncthreads();   // new h + partials visible

            // reduce + emit output for step t (64 threads; overlaps next MMAs)
            if (tid < BT) {
                const float4* Pq = (const float4*)(Ppart + (t & 1) * 1024 + tid * 16);
                float2 a = *Bemb;
                #pragma unroll
                for (int q = 0; q < 8; q++) {
                    float4 v = Pq[q];
                    a.x += v.x + v.z;
                    a.y += v.y + v.w;
                }
                int bgl = bbase + tid;
                if (bgl < B) *(float2*)&out[(size_t)(bgl * 30 + t) * 2] = a;
            }
            { unsigned* tp = HhiC; HhiC = HhiN; HhiN = tp; }
            { unsigned* tp = HloC; HloC = HloN; HloN = tp; }
        }
    }
}

extern "C" void kernel_launch(void* const* d_in, const int* in_sizes, int n_in,
                              void* d_out, int out_size)
{
    const float* traj  = (const float*)d_in[0];
    const float* cl    = (const float*)d_in[1];
    const float* Wih_c = (const float*)d_in[2];
    const float* Whh_c = (const float*)d_in[3];
    const float* bih_c = (const float*)d_in[4];
    const float* bhh_c = (const float*)d_in[5];
    const float* Wih_e = (const float*)d_in[6];
    const float* Whh_e = (const float*)d_in[7];
    const float* bih_e = (const float*)d_in[8];
    const float* bhh_e = (const float*)d_in[9];
    const float* Wih_d = (const float*)d_in[10];
    const float* Whh_d = (const float*)d_in[11];
    const float* bih_d = (const float*)d_in[12];
    const float* bhh_d = (const float*)d_in[13];
    const float* W_emb = (const float*)d_in[14];
    const float* b_emb = (const float*)d_in[15];

    int B = in_sizes[0] / 40;
    int grid = (B + BT - 1) / BT;

    cudaFuncSetAttribute(lstm_fused_kernel,
                         cudaFuncAttributeMaxDynamicSharedMemorySize, SMEM_BYTES);
    lstm_fused_kernel<<<grid, TPB, SMEM_BYTES>>>(
        traj, cl, Wih_c, Whh_c, bih_c, bhh_c,
        Wih_e, Whh_e, bih_e, bhh_e,
        Wih_d, Whh_d, bih_d, bhh_d,
        W_emb, b_emb, (float*)d_out, B);
}